// round 1
// baseline (speedup 1.0000x reference)
#include <cuda_runtime.h>
#include <math.h>

#define BB 2
#define TT 2048
#define CC 2048
#define NH 32
#define NG 8
#define HD 64

// ---------------- scratch (no allocations allowed) ----------------
__device__ float g_QP[BB * TT * CC];        // (B*T, 2048)  Q projection
__device__ float g_KP[BB * TT * NG * HD];   // (B*T, 512)   K projection
__device__ float g_VP[BB * TT * NG * HD];   // (B*T, 512)   V projection
__device__ float g_O [BB * TT * CC];        // (B*T, 2048)  attention output

// ---------------- NT GEMM: C[m][n] = sum_k A[m][k] * B[n][k] + bias[n] ----------------
// A: MxK row-major, B: NxK row-major. 128x128x8 tiles, 8x8 per thread, 256 threads.
__global__ void __launch_bounds__(256) gemm_nt(
    const float* __restrict__ A, const float* __restrict__ Bm,
    const float* __restrict__ bias, float* __restrict__ Cm,
    int M, int N, int K)
{
    constexpr int BM = 128, BN = 128, BK = 8, TM = 8, TN = 8;
    __shared__ float As[BK][BM];
    __shared__ float Bs[BK][BN];

    const int tid  = threadIdx.x;
    const int bm   = blockIdx.y * BM;
    const int bn   = blockIdx.x * BN;
    const int tRow = tid / 16;
    const int tCol = tid % 16;

    float acc[TM][TN];
#pragma unroll
    for (int i = 0; i < TM; i++)
#pragma unroll
        for (int j = 0; j < TN; j++) acc[i][j] = 0.f;

    const int lRow = tid >> 1;          // 0..127
    const int lCol = (tid & 1) * 4;     // 0 or 4
    const float* Ag = A  + (size_t)(bm + lRow) * K + lCol;
    const float* Bg = Bm + (size_t)(bn + lRow) * K + lCol;

    for (int k0 = 0; k0 < K; k0 += BK) {
        float4 a4 = *(const float4*)(Ag + k0);
        float4 b4 = *(const float4*)(Bg + k0);
        As[lCol + 0][lRow] = a4.x; As[lCol + 1][lRow] = a4.y;
        As[lCol + 2][lRow] = a4.z; As[lCol + 3][lRow] = a4.w;
        Bs[lCol + 0][lRow] = b4.x; Bs[lCol + 1][lRow] = b4.y;
        Bs[lCol + 2][lRow] = b4.z; Bs[lCol + 3][lRow] = b4.w;
        __syncthreads();

#pragma unroll
        for (int k = 0; k < BK; k++) {
            float rm[TM], rn[TN];
#pragma unroll
            for (int i = 0; i < TM; i++) rm[i] = As[k][tRow * TM + i];
#pragma unroll
            for (int j = 0; j < TN; j++) rn[j] = Bs[k][tCol * TN + j];
#pragma unroll
            for (int i = 0; i < TM; i++)
#pragma unroll
                for (int j = 0; j < TN; j++) acc[i][j] += rm[i] * rn[j];
        }
        __syncthreads();
    }

    float bb[TN];
#pragma unroll
    for (int j = 0; j < TN; j++)
        bb[j] = bias ? bias[bn + tCol * TN + j] : 0.f;

#pragma unroll
    for (int i = 0; i < TM; i++) {
        int row = bm + tRow * TM + i;
        float* Cp = Cm + (size_t)row * N + bn + tCol * TN;
        float4 v0 = make_float4(acc[i][0] + bb[0], acc[i][1] + bb[1],
                                acc[i][2] + bb[2], acc[i][3] + bb[3]);
        float4 v1 = make_float4(acc[i][4] + bb[4], acc[i][5] + bb[5],
                                acc[i][6] + bb[6], acc[i][7] + bb[7]);
        ((float4*)Cp)[0] = v0;
        ((float4*)Cp)[1] = v1;
    }
}

// ---------------- flash attention, fp32, 64x64 tiles ----------------
// grid: (T/64, B*NH). block: 256 threads as 16x16, 4x4 frags.
// head h -> KV group g = h % NG. softmax over full T (non-causal).
#define SPAD 65
__global__ void __launch_bounds__(256) attn_kernel(
    const float* __restrict__ QP, const float* __restrict__ KP,
    const float* __restrict__ VP, float* __restrict__ O)
{
    __shared__ float Qs[64][SPAD];
    __shared__ float Ks[64][SPAD];
    __shared__ float Vs[64][SPAD];
    __shared__ float Ps[64][SPAD];

    const int bh = blockIdx.y;
    const int b  = bh >> 5;
    const int h  = bh & 31;
    const int g  = h & 7;
    const int q0 = blockIdx.x * 64;

    const float* Qp = QP + ((size_t)b * TT + q0) * CC + h * HD;
    const float* Kp = KP + (size_t)b * TT * (NG * HD) + g * HD;
    const float* Vp = VP + (size_t)b * TT * (NG * HD) + g * HD;

    const int tid = threadIdx.x;
    const int ty  = tid >> 4;     // 0..15
    const int tx  = tid & 15;     // 0..15

    // load Q tile (pre-scaled by 1/sqrt(HD))
#pragma unroll
    for (int it = 0; it < 4; it++) {
        int idx = tid + it * 256;         // float4 index, 0..1023
        int r = idx >> 4, c = (idx & 15) * 4;
        float4 v = *(const float4*)(Qp + (size_t)r * CC + c);
        Qs[r][c + 0] = v.x * 0.125f; Qs[r][c + 1] = v.y * 0.125f;
        Qs[r][c + 2] = v.z * 0.125f; Qs[r][c + 3] = v.w * 0.125f;
    }

    float m_i[4], l_i[4], o[4][4];
#pragma unroll
    for (int i = 0; i < 4; i++) {
        m_i[i] = -INFINITY; l_i[i] = 0.f;
#pragma unroll
        for (int j = 0; j < 4; j++) o[i][j] = 0.f;
    }
    __syncthreads();

    for (int kv = 0; kv < TT; kv += 64) {
        // load K,V tiles (row = key index, col = d)
#pragma unroll
        for (int it = 0; it < 4; it++) {
            int idx = tid + it * 256;
            int r = idx >> 4, c = (idx & 15) * 4;
            float4 kv4 = *(const float4*)(Kp + (size_t)(kv + r) * (NG * HD) + c);
            float4 vv4 = *(const float4*)(Vp + (size_t)(kv + r) * (NG * HD) + c);
            Ks[r][c + 0] = kv4.x; Ks[r][c + 1] = kv4.y;
            Ks[r][c + 2] = kv4.z; Ks[r][c + 3] = kv4.w;
            Vs[r][c + 0] = vv4.x; Vs[r][c + 1] = vv4.y;
            Vs[r][c + 2] = vv4.z; Vs[r][c + 3] = vv4.w;
        }
        __syncthreads();

        // S = Q @ K^T  (4x4 frag per thread)
        float s[4][4];
#pragma unroll
        for (int i = 0; i < 4; i++)
#pragma unroll
            for (int j = 0; j < 4; j++) s[i][j] = 0.f;
#pragma unroll
        for (int d = 0; d < 64; d++) {
            float qr[4], kr[4];
#pragma unroll
            for (int i = 0; i < 4; i++) qr[i] = Qs[ty * 4 + i][d];
#pragma unroll
            for (int j = 0; j < 4; j++) kr[j] = Ks[tx * 4 + j][d];
#pragma unroll
            for (int i = 0; i < 4; i++)
#pragma unroll
                for (int j = 0; j < 4; j++) s[i][j] += qr[i] * kr[j];
        }

        // row max across 16-lane tx groups
        float rmax[4];
#pragma unroll
        for (int i = 0; i < 4; i++) {
            float mx = s[i][0];
#pragma unroll
            for (int j = 1; j < 4; j++) mx = fmaxf(mx, s[i][j]);
#pragma unroll
            for (int off = 1; off < 16; off <<= 1)
                mx = fmaxf(mx, __shfl_xor_sync(0xffffffffu, mx, off));
            rmax[i] = mx;
        }

        float rsum[4];
#pragma unroll
        for (int i = 0; i < 4; i++) {
            float mnew = fmaxf(m_i[i], rmax[i]);
            float sc   = __expf(m_i[i] - mnew);
            m_i[i] = mnew;
            float acc = 0.f;
#pragma unroll
            for (int j = 0; j < 4; j++) {
                s[i][j] = __expf(s[i][j] - mnew);
                acc += s[i][j];
            }
#pragma unroll
            for (int off = 1; off < 16; off <<= 1)
                acc += __shfl_xor_sync(0xffffffffu, acc, off);
            rsum[i] = acc;
            l_i[i] = l_i[i] * sc + rsum[i];
#pragma unroll
            for (int j = 0; j < 4; j++) o[i][j] *= sc;
        }

        // stage P to smem (s-dim must be shared across tx)
#pragma unroll
        for (int i = 0; i < 4; i++)
#pragma unroll
            for (int j = 0; j < 4; j++)
                Ps[ty * 4 + i][tx * 4 + j] = s[i][j];
        __syncthreads();

        // O += P @ V
#pragma unroll
        for (int kk = 0; kk < 64; kk++) {
            float pr[4], vr[4];
#pragma unroll
            for (int i = 0; i < 4; i++) pr[i] = Ps[ty * 4 + i][kk];
#pragma unroll
            for (int j = 0; j < 4; j++) vr[j] = Vs[kk][tx * 4 + j];
#pragma unroll
            for (int i = 0; i < 4; i++)
#pragma unroll
                for (int j = 0; j < 4; j++) o[i][j] += pr[i] * vr[j];
        }
        __syncthreads();
    }

    // normalize + store
    float* Op = O + ((size_t)b * TT + q0) * CC + h * HD;
#pragma unroll
    for (int i = 0; i < 4; i++) {
        float inv = 1.0f / l_i[i];
#pragma unroll
        for (int j = 0; j < 4; j++)
            Op[(size_t)(ty * 4 + i) * CC + tx * 4 + j] = o[i][j] * inv;
    }
}

// ---------------- launch ----------------
extern "C" void kernel_launch(void* const* d_in, const int* in_sizes, int n_in,
                              void* d_out, int out_size)
{
    const float* q  = (const float*)d_in[0];
    const float* k  = (const float*)d_in[1];
    const float* v  = (const float*)d_in[2];
    const float* Wq = (const float*)d_in[3];
    const float* Wk = (const float*)d_in[4];
    const float* Wv = (const float*)d_in[5];
    const float* Wp = (const float*)d_in[6];
    const float* bp = (const float*)d_in[7];
    float* out = (float*)d_out;

    float *pQP, *pKP, *pVP, *pO;
    cudaGetSymbolAddress((void**)&pQP, g_QP);
    cudaGetSymbolAddress((void**)&pKP, g_KP);
    cudaGetSymbolAddress((void**)&pVP, g_VP);
    cudaGetSymbolAddress((void**)&pO,  g_O);

    const int M = BB * TT;  // 4096

    // projections
    gemm_nt<<<dim3(CC / 128, M / 128), 256>>>(q, Wq, nullptr, pQP, M, CC, CC);
    gemm_nt<<<dim3((NG * HD) / 128, M / 128), 256>>>(k, Wk, nullptr, pKP, M, NG * HD, CC);
    gemm_nt<<<dim3((NG * HD) / 128, M / 128), 256>>>(v, Wv, nullptr, pVP, M, NG * HD, CC);

    // attention
    attn_kernel<<<dim3(TT / 64, BB * NH), 256>>>(pQP, pKP, pVP, pO);

    // output projection + bias
    gemm_nt<<<dim3(CC / 128, M / 128), 256>>>(pO, Wp, bp, out, M, CC, CC);
}

// round 3
// speedup vs baseline: 1.5949x; 1.5949x over previous
#include <cuda_runtime.h>
#include <cstdint>
#include <math.h>

#define BB 2
#define TT 2048
#define CC 2048
#define NH 32
#define NG 8
#define HD 64

// ---------------- scratch (no allocations allowed) ----------------
__device__ float g_QP[BB * TT * CC];        // (B*T, 2048)  Q projection
__device__ float g_KP[BB * TT * NG * HD];   // (B*T, 512)   K projection
__device__ float g_VP[BB * TT * NG * HD];   // (B*T, 512)   V projection
__device__ float g_O [BB * TT * CC];        // (B*T, 2048)  attention output

// ---------------- helpers ----------------
__device__ __forceinline__ uint32_t f2tf32(float x) {
    uint32_t r;
    asm("cvt.rna.tf32.f32 %0, %1;" : "=r"(r) : "f"(x));
    return r;
}
__device__ __forceinline__ void mma_tf32(float& d0, float& d1, float& d2, float& d3,
                                         uint32_t a0, uint32_t a1, uint32_t a2, uint32_t a3,
                                         uint32_t b0, uint32_t b1)
{
    asm volatile(
        "mma.sync.aligned.m16n8k8.row.col.f32.tf32.tf32.f32 "
        "{%0,%1,%2,%3}, {%4,%5,%6,%7}, {%8,%9}, {%0,%1,%2,%3};"
        : "+f"(d0), "+f"(d1), "+f"(d2), "+f"(d3)
        : "r"(a0), "r"(a1), "r"(a2), "r"(a3), "r"(b0), "r"(b1));
}

// ============== tf32 mma.sync NT GEMM: C[m][n] = sum_k A[m][k]*B[n][k] (+bias) ==============
// 128x128 CTA tile, BK=16, 256 threads = 8 warps (2m x 4n), warp tile 64x32.
// SMEM rows stride 20 floats (conflict-free staging + fragment loads).
#define GST 20                                  // smem row stride (floats)
#define GEMM_SMEM_BYTES (2 * 2 * 128 * GST * 4) // 81920

__global__ void __launch_bounds__(256) gemm_nt_mma(
    const float* __restrict__ A, const float* __restrict__ Bm,
    const float* __restrict__ bias, float* __restrict__ Cm,
    int M, int N, int K)
{
    extern __shared__ float smem[];
    // layout: As[2][128*GST], Bs[2][128*GST]
    float* As0 = smem;
    float* Bs0 = smem + 2 * 128 * GST;

    const int tid  = threadIdx.x;
    const int wid  = tid >> 5;
    const int lane = tid & 31;
    const int grp  = lane >> 2;    // 0..7
    const int tig  = lane & 3;     // 0..3

    const int warp_m = wid >> 2;   // 0..1
    const int warp_n = wid & 3;    // 0..3

    const int bm = blockIdx.y * 128;
    const int bn = blockIdx.x * 128;

    // staging: thread t handles float4 slots t and t+256 of the 128x16 tile
    const int srow = tid >> 2;          // 0..63  (and +64)
    const int scg  = (tid & 3) * 4;     // col 0,4,8,12
    const float* Ag = A  + (size_t)(bm + srow) * K + scg;
    const float* Bg = Bm + (size_t)(bn + srow) * K + scg;
    const int sidx = srow * GST + scg;  // smem float offset (and +64*GST)

    float acc[4][4][4];
#pragma unroll
    for (int i = 0; i < 4; i++)
#pragma unroll
        for (int j = 0; j < 4; j++)
#pragma unroll
            for (int r = 0; r < 4; r++) acc[i][j][r] = 0.f;

    const int NSTAGE = K / 16;
    float4 ra0, ra1, rb0, rb1;

    // prologue: stage 0 -> regs -> smem buf0; stage 1 -> regs
    ra0 = *(const float4*)(Ag);
    ra1 = *(const float4*)(Ag + 64 * (size_t)K);
    rb0 = *(const float4*)(Bg);
    rb1 = *(const float4*)(Bg + 64 * (size_t)K);
    {
        uint32_t* a0p = (uint32_t*)(As0 + sidx);
        uint32_t* a1p = (uint32_t*)(As0 + sidx + 64 * GST);
        uint32_t* b0p = (uint32_t*)(Bs0 + sidx);
        uint32_t* b1p = (uint32_t*)(Bs0 + sidx + 64 * GST);
        a0p[0]=f2tf32(ra0.x); a0p[1]=f2tf32(ra0.y); a0p[2]=f2tf32(ra0.z); a0p[3]=f2tf32(ra0.w);
        a1p[0]=f2tf32(ra1.x); a1p[1]=f2tf32(ra1.y); a1p[2]=f2tf32(ra1.z); a1p[3]=f2tf32(ra1.w);
        b0p[0]=f2tf32(rb0.x); b0p[1]=f2tf32(rb0.y); b0p[2]=f2tf32(rb0.z); b0p[3]=f2tf32(rb0.w);
        b1p[0]=f2tf32(rb1.x); b1p[1]=f2tf32(rb1.y); b1p[2]=f2tf32(rb1.z); b1p[3]=f2tf32(rb1.w);
    }
    if (NSTAGE > 1) {
        ra0 = *(const float4*)(Ag + 16);
        ra1 = *(const float4*)(Ag + 64 * (size_t)K + 16);
        rb0 = *(const float4*)(Bg + 16);
        rb1 = *(const float4*)(Bg + 64 * (size_t)K + 16);
    }
    __syncthreads();

    for (int s = 0; s < NSTAGE; s++) {
        // store stage s+1 into the other buffer (its previous contents were consumed in iter s-1)
        if (s + 1 < NSTAGE) {
            const int nb = (s + 1) & 1;
            uint32_t* a0p = (uint32_t*)(As0 + nb * 128 * GST + sidx);
            uint32_t* a1p = (uint32_t*)(As0 + nb * 128 * GST + sidx + 64 * GST);
            uint32_t* b0p = (uint32_t*)(Bs0 + nb * 128 * GST + sidx);
            uint32_t* b1p = (uint32_t*)(Bs0 + nb * 128 * GST + sidx + 64 * GST);
            a0p[0]=f2tf32(ra0.x); a0p[1]=f2tf32(ra0.y); a0p[2]=f2tf32(ra0.z); a0p[3]=f2tf32(ra0.w);
            a1p[0]=f2tf32(ra1.x); a1p[1]=f2tf32(ra1.y); a1p[2]=f2tf32(ra1.z); a1p[3]=f2tf32(ra1.w);
            b0p[0]=f2tf32(rb0.x); b0p[1]=f2tf32(rb0.y); b0p[2]=f2tf32(rb0.z); b0p[3]=f2tf32(rb0.w);
            b1p[0]=f2tf32(rb1.x); b1p[1]=f2tf32(rb1.y); b1p[2]=f2tf32(rb1.z); b1p[3]=f2tf32(rb1.w);
        }
        // prefetch stage s+2
        if (s + 2 < NSTAGE) {
            const int k0 = (s + 2) * 16;
            ra0 = *(const float4*)(Ag + k0);
            ra1 = *(const float4*)(Ag + 64 * (size_t)K + k0);
            rb0 = *(const float4*)(Bg + k0);
            rb1 = *(const float4*)(Bg + 64 * (size_t)K + k0);
        }

        // compute on buffer s&1
        const float* Asb = As0 + (s & 1) * 128 * GST;
        const float* Bsb = Bs0 + (s & 1) * 128 * GST;
#pragma unroll
        for (int kk = 0; kk < 16; kk += 8) {
            uint32_t bfr[4][2];
#pragma unroll
            for (int na = 0; na < 4; na++) {
                const uint32_t* bp = (const uint32_t*)(Bsb + (warp_n * 32 + na * 8 + grp) * GST + kk + tig);
                bfr[na][0] = bp[0];
                bfr[na][1] = bp[4];
            }
#pragma unroll
            for (int ma = 0; ma < 4; ma++) {
                const uint32_t* ap0 = (const uint32_t*)(Asb + (warp_m * 64 + ma * 16 + grp) * GST + kk + tig);
                const uint32_t* ap1 = (const uint32_t*)(Asb + (warp_m * 64 + ma * 16 + 8 + grp) * GST + kk + tig);
                uint32_t a0 = ap0[0], a1 = ap1[0], a2 = ap0[4], a3 = ap1[4];
#pragma unroll
                for (int na = 0; na < 4; na++) {
                    mma_tf32(acc[ma][na][0], acc[ma][na][1], acc[ma][na][2], acc[ma][na][3],
                             a0, a1, a2, a3, bfr[na][0], bfr[na][1]);
                }
            }
        }
        __syncthreads();
    }

    // epilogue: direct coalesced float2 stores (+bias)
#pragma unroll
    for (int na = 0; na < 4; na++) {
        const int col = bn + warp_n * 32 + na * 8 + 2 * tig;
        float b0 = 0.f, b1 = 0.f;
        if (bias) { b0 = bias[col]; b1 = bias[col + 1]; }
#pragma unroll
        for (int ma = 0; ma < 4; ma++) {
            const int row = bm + warp_m * 64 + ma * 16 + grp;
            float2 v0 = make_float2(acc[ma][na][0] + b0, acc[ma][na][1] + b1);
            float2 v1 = make_float2(acc[ma][na][2] + b0, acc[ma][na][3] + b1);
            *(float2*)(Cm + (size_t)row * N + col) = v0;
            *(float2*)(Cm + (size_t)(row + 8) * N + col) = v1;
        }
    }
}

// ---------------- flash attention, fp32, 64x64 tiles (unchanged) ----------------
#define SPAD 65
__global__ void __launch_bounds__(256) attn_kernel(
    const float* __restrict__ QP, const float* __restrict__ KP,
    const float* __restrict__ VP, float* __restrict__ O)
{
    __shared__ float Qs[64][SPAD];
    __shared__ float Ks[64][SPAD];
    __shared__ float Vs[64][SPAD];
    __shared__ float Ps[64][SPAD];

    const int bh = blockIdx.y;
    const int b  = bh >> 5;
    const int h  = bh & 31;
    const int g  = h & 7;
    const int q0 = blockIdx.x * 64;

    const float* Qp = QP + ((size_t)b * TT + q0) * CC + h * HD;
    const float* Kp = KP + (size_t)b * TT * (NG * HD) + g * HD;
    const float* Vp = VP + (size_t)b * TT * (NG * HD) + g * HD;

    const int tid = threadIdx.x;
    const int ty  = tid >> 4;
    const int tx  = tid & 15;

#pragma unroll
    for (int it = 0; it < 4; it++) {
        int idx = tid + it * 256;
        int r = idx >> 4, c = (idx & 15) * 4;
        float4 v = *(const float4*)(Qp + (size_t)r * CC + c);
        Qs[r][c + 0] = v.x * 0.125f; Qs[r][c + 1] = v.y * 0.125f;
        Qs[r][c + 2] = v.z * 0.125f; Qs[r][c + 3] = v.w * 0.125f;
    }

    float m_i[4], l_i[4], o[4][4];
#pragma unroll
    for (int i = 0; i < 4; i++) {
        m_i[i] = -INFINITY; l_i[i] = 0.f;
#pragma unroll
        for (int j = 0; j < 4; j++) o[i][j] = 0.f;
    }
    __syncthreads();

    for (int kv = 0; kv < TT; kv += 64) {
#pragma unroll
        for (int it = 0; it < 4; it++) {
            int idx = tid + it * 256;
            int r = idx >> 4, c = (idx & 15) * 4;
            float4 kv4 = *(const float4*)(Kp + (size_t)(kv + r) * (NG * HD) + c);
            float4 vv4 = *(const float4*)(Vp + (size_t)(kv + r) * (NG * HD) + c);
            Ks[r][c + 0] = kv4.x; Ks[r][c + 1] = kv4.y;
            Ks[r][c + 2] = kv4.z; Ks[r][c + 3] = kv4.w;
            Vs[r][c + 0] = vv4.x; Vs[r][c + 1] = vv4.y;
            Vs[r][c + 2] = vv4.z; Vs[r][c + 3] = vv4.w;
        }
        __syncthreads();

        float s[4][4];
#pragma unroll
        for (int i = 0; i < 4; i++)
#pragma unroll
            for (int j = 0; j < 4; j++) s[i][j] = 0.f;
#pragma unroll
        for (int d = 0; d < 64; d++) {
            float qr[4], kr[4];
#pragma unroll
            for (int i = 0; i < 4; i++) qr[i] = Qs[ty * 4 + i][d];
#pragma unroll
            for (int j = 0; j < 4; j++) kr[j] = Ks[tx * 4 + j][d];
#pragma unroll
            for (int i = 0; i < 4; i++)
#pragma unroll
                for (int j = 0; j < 4; j++) s[i][j] += qr[i] * kr[j];
        }

        float rmax[4];
#pragma unroll
        for (int i = 0; i < 4; i++) {
            float mx = s[i][0];
#pragma unroll
            for (int j = 1; j < 4; j++) mx = fmaxf(mx, s[i][j]);
#pragma unroll
            for (int off = 1; off < 16; off <<= 1)
                mx = fmaxf(mx, __shfl_xor_sync(0xffffffffu, mx, off));
            rmax[i] = mx;
        }

        float rsum[4];
#pragma unroll
        for (int i = 0; i < 4; i++) {
            float mnew = fmaxf(m_i[i], rmax[i]);
            float sc   = __expf(m_i[i] - mnew);
            m_i[i] = mnew;
            float acc = 0.f;
#pragma unroll
            for (int j = 0; j < 4; j++) {
                s[i][j] = __expf(s[i][j] - mnew);
                acc += s[i][j];
            }
#pragma unroll
            for (int off = 1; off < 16; off <<= 1)
                acc += __shfl_xor_sync(0xffffffffu, acc, off);
            rsum[i] = acc;
            l_i[i] = l_i[i] * sc + rsum[i];
#pragma unroll
            for (int j = 0; j < 4; j++) o[i][j] *= sc;
        }

#pragma unroll
        for (int i = 0; i < 4; i++)
#pragma unroll
            for (int j = 0; j < 4; j++)
                Ps[ty * 4 + i][tx * 4 + j] = s[i][j];
        __syncthreads();

#pragma unroll
        for (int kk = 0; kk < 64; kk++) {
            float pr[4], vr[4];
#pragma unroll
            for (int i = 0; i < 4; i++) pr[i] = Ps[ty * 4 + i][kk];
#pragma unroll
            for (int j = 0; j < 4; j++) vr[j] = Vs[kk][tx * 4 + j];
#pragma unroll
            for (int i = 0; i < 4; i++)
#pragma unroll
                for (int j = 0; j < 4; j++) o[i][j] += pr[i] * vr[j];
        }
        __syncthreads();
    }

    float* Op = O + ((size_t)b * TT + q0) * CC + h * HD;
#pragma unroll
    for (int i = 0; i < 4; i++) {
        float inv = 1.0f / l_i[i];
#pragma unroll
        for (int j = 0; j < 4; j++)
            Op[(size_t)(ty * 4 + i) * CC + tx * 4 + j] = o[i][j] * inv;
    }
}

// ---------------- launch ----------------
extern "C" void kernel_launch(void* const* d_in, const int* in_sizes, int n_in,
                              void* d_out, int out_size)
{
    const float* q  = (const float*)d_in[0];
    const float* k  = (const float*)d_in[1];
    const float* v  = (const float*)d_in[2];
    const float* Wq = (const float*)d_in[3];
    const float* Wk = (const float*)d_in[4];
    const float* Wv = (const float*)d_in[5];
    const float* Wp = (const float*)d_in[6];
    const float* bp = (const float*)d_in[7];
    float* out = (float*)d_out;

    float *pQP, *pKP, *pVP, *pO;
    cudaGetSymbolAddress((void**)&pQP, g_QP);
    cudaGetSymbolAddress((void**)&pKP, g_KP);
    cudaGetSymbolAddress((void**)&pVP, g_VP);
    cudaGetSymbolAddress((void**)&pO,  g_O);

    cudaFuncSetAttribute(gemm_nt_mma, cudaFuncAttributeMaxDynamicSharedMemorySize, GEMM_SMEM_BYTES);

    const int M = BB * TT;  // 4096

    // projections (tf32 mma.sync)
    gemm_nt_mma<<<dim3(CC / 128, M / 128), 256, GEMM_SMEM_BYTES>>>(q, Wq, nullptr, pQP, M, CC, CC);
    gemm_nt_mma<<<dim3((NG * HD) / 128, M / 128), 256, GEMM_SMEM_BYTES>>>(k, Wk, nullptr, pKP, M, NG * HD, CC);
    gemm_nt_mma<<<dim3((NG * HD) / 128, M / 128), 256, GEMM_SMEM_BYTES>>>(v, Wv, nullptr, pVP, M, NG * HD, CC);

    // attention (fp32 SIMT, unchanged)
    attn_kernel<<<dim3(TT / 64, BB * NH), 256>>>(pQP, pKP, pVP, pO);

    // output projection + bias (tf32 mma.sync)
    gemm_nt_mma<<<dim3(CC / 128, M / 128), 256, GEMM_SMEM_BYTES>>>(pO, Wp, bp, out, M, CC, CC);
}

// round 4
// speedup vs baseline: 3.0199x; 1.8935x over previous
#include <cuda_runtime.h>
#include <cuda_bf16.h>
#include <cstdint>
#include <math.h>

#define BB 2
#define TT 2048
#define CC 2048
#define NH 32
#define NG 8
#define HD 64

// ---------------- scratch (no allocations allowed) ----------------
__device__ float g_QP[BB * TT * CC];        // (B*T, 2048)  Q projection
__device__ float g_KP[BB * TT * NG * HD];   // (B*T, 512)   K projection
__device__ float g_VP[BB * TT * NG * HD];   // (B*T, 512)   V projection
__device__ float g_O [BB * TT * CC];        // (B*T, 2048)  attention output

// ---------------- helpers ----------------
__device__ __forceinline__ uint32_t f2tf32(float x) {
    uint32_t r;
    asm("cvt.rna.tf32.f32 %0, %1;" : "=r"(r) : "f"(x));
    return r;
}
__device__ __forceinline__ void mma_tf32(float& d0, float& d1, float& d2, float& d3,
                                         uint32_t a0, uint32_t a1, uint32_t a2, uint32_t a3,
                                         uint32_t b0, uint32_t b1)
{
    asm volatile(
        "mma.sync.aligned.m16n8k8.row.col.f32.tf32.tf32.f32 "
        "{%0,%1,%2,%3}, {%4,%5,%6,%7}, {%8,%9}, {%0,%1,%2,%3};"
        : "+f"(d0), "+f"(d1), "+f"(d2), "+f"(d3)
        : "r"(a0), "r"(a1), "r"(a2), "r"(a3), "r"(b0), "r"(b1));
}
__device__ __forceinline__ void mma_bf16(float* d,
                                         uint32_t a0, uint32_t a1, uint32_t a2, uint32_t a3,
                                         uint32_t b0, uint32_t b1)
{
    asm volatile(
        "mma.sync.aligned.m16n8k16.row.col.f32.bf16.bf16.f32 "
        "{%0,%1,%2,%3}, {%4,%5,%6,%7}, {%8,%9}, {%0,%1,%2,%3};"
        : "+f"(d[0]), "+f"(d[1]), "+f"(d[2]), "+f"(d[3])
        : "r"(a0), "r"(a1), "r"(a2), "r"(a3), "r"(b0), "r"(b1));
}
__device__ __forceinline__ uint32_t packbf2(float a, float b) {
    __nv_bfloat162 t = __floats2bfloat162_rn(a, b);   // a -> low half (smaller k index)
    return *(uint32_t*)&t;
}
// split pair (a,b) into hi word + lo word (2-term bf16 decomposition)
__device__ __forceinline__ void split2(float a, float b, uint32_t& hi, uint32_t& lo) {
    __nv_bfloat16 ah = __float2bfloat16_rn(a);
    __nv_bfloat16 bh = __float2bfloat16_rn(b);
    float ar = a - __bfloat162float(ah);
    float br = b - __bfloat162float(bh);
    __nv_bfloat162 h; h.x = ah; h.y = bh;
    hi = *(uint32_t*)&h;
    lo = packbf2(ar, br);
}

// ============== tf32 mma.sync NT GEMM (unchanged from R3) ==============
#define GST 20
#define GEMM_SMEM_BYTES (2 * 2 * 128 * GST * 4)

__global__ void __launch_bounds__(256) gemm_nt_mma(
    const float* __restrict__ A, const float* __restrict__ Bm,
    const float* __restrict__ bias, float* __restrict__ Cm,
    int M, int N, int K)
{
    extern __shared__ float smem[];
    float* As0 = smem;
    float* Bs0 = smem + 2 * 128 * GST;

    const int tid  = threadIdx.x;
    const int wid  = tid >> 5;
    const int lane = tid & 31;
    const int grp  = lane >> 2;
    const int tig  = lane & 3;
    const int warp_m = wid >> 2;
    const int warp_n = wid & 3;
    const int bm = blockIdx.y * 128;
    const int bn = blockIdx.x * 128;

    const int srow = tid >> 2;
    const int scg  = (tid & 3) * 4;
    const float* Ag = A  + (size_t)(bm + srow) * K + scg;
    const float* Bg = Bm + (size_t)(bn + srow) * K + scg;
    const int sidx = srow * GST + scg;

    float acc[4][4][4];
#pragma unroll
    for (int i = 0; i < 4; i++)
#pragma unroll
        for (int j = 0; j < 4; j++)
#pragma unroll
            for (int r = 0; r < 4; r++) acc[i][j][r] = 0.f;

    const int NSTAGE = K / 16;
    float4 ra0, ra1, rb0, rb1;

    ra0 = *(const float4*)(Ag);
    ra1 = *(const float4*)(Ag + 64 * (size_t)K);
    rb0 = *(const float4*)(Bg);
    rb1 = *(const float4*)(Bg + 64 * (size_t)K);
    {
        uint32_t* a0p = (uint32_t*)(As0 + sidx);
        uint32_t* a1p = (uint32_t*)(As0 + sidx + 64 * GST);
        uint32_t* b0p = (uint32_t*)(Bs0 + sidx);
        uint32_t* b1p = (uint32_t*)(Bs0 + sidx + 64 * GST);
        a0p[0]=f2tf32(ra0.x); a0p[1]=f2tf32(ra0.y); a0p[2]=f2tf32(ra0.z); a0p[3]=f2tf32(ra0.w);
        a1p[0]=f2tf32(ra1.x); a1p[1]=f2tf32(ra1.y); a1p[2]=f2tf32(ra1.z); a1p[3]=f2tf32(ra1.w);
        b0p[0]=f2tf32(rb0.x); b0p[1]=f2tf32(rb0.y); b0p[2]=f2tf32(rb0.z); b0p[3]=f2tf32(rb0.w);
        b1p[0]=f2tf32(rb1.x); b1p[1]=f2tf32(rb1.y); b1p[2]=f2tf32(rb1.z); b1p[3]=f2tf32(rb1.w);
    }
    if (NSTAGE > 1) {
        ra0 = *(const float4*)(Ag + 16);
        ra1 = *(const float4*)(Ag + 64 * (size_t)K + 16);
        rb0 = *(const float4*)(Bg + 16);
        rb1 = *(const float4*)(Bg + 64 * (size_t)K + 16);
    }
    __syncthreads();

    for (int s = 0; s < NSTAGE; s++) {
        if (s + 1 < NSTAGE) {
            const int nb = (s + 1) & 1;
            uint32_t* a0p = (uint32_t*)(As0 + nb * 128 * GST + sidx);
            uint32_t* a1p = (uint32_t*)(As0 + nb * 128 * GST + sidx + 64 * GST);
            uint32_t* b0p = (uint32_t*)(Bs0 + nb * 128 * GST + sidx);
            uint32_t* b1p = (uint32_t*)(Bs0 + nb * 128 * GST + sidx + 64 * GST);
            a0p[0]=f2tf32(ra0.x); a0p[1]=f2tf32(ra0.y); a0p[2]=f2tf32(ra0.z); a0p[3]=f2tf32(ra0.w);
            a1p[0]=f2tf32(ra1.x); a1p[1]=f2tf32(ra1.y); a1p[2]=f2tf32(ra1.z); a1p[3]=f2tf32(ra1.w);
            b0p[0]=f2tf32(rb0.x); b0p[1]=f2tf32(rb0.y); b0p[2]=f2tf32(rb0.z); b0p[3]=f2tf32(rb0.w);
            b1p[0]=f2tf32(rb1.x); b1p[1]=f2tf32(rb1.y); b1p[2]=f2tf32(rb1.z); b1p[3]=f2tf32(rb1.w);
        }
        if (s + 2 < NSTAGE) {
            const int k0 = (s + 2) * 16;
            ra0 = *(const float4*)(Ag + k0);
            ra1 = *(const float4*)(Ag + 64 * (size_t)K + k0);
            rb0 = *(const float4*)(Bg + k0);
            rb1 = *(const float4*)(Bg + 64 * (size_t)K + k0);
        }

        const float* Asb = As0 + (s & 1) * 128 * GST;
        const float* Bsb = Bs0 + (s & 1) * 128 * GST;
#pragma unroll
        for (int kk = 0; kk < 16; kk += 8) {
            uint32_t bfr[4][2];
#pragma unroll
            for (int na = 0; na < 4; na++) {
                const uint32_t* bp = (const uint32_t*)(Bsb + (warp_n * 32 + na * 8 + grp) * GST + kk + tig);
                bfr[na][0] = bp[0];
                bfr[na][1] = bp[4];
            }
#pragma unroll
            for (int ma = 0; ma < 4; ma++) {
                const uint32_t* ap0 = (const uint32_t*)(Asb + (warp_m * 64 + ma * 16 + grp) * GST + kk + tig);
                const uint32_t* ap1 = (const uint32_t*)(Asb + (warp_m * 64 + ma * 16 + 8 + grp) * GST + kk + tig);
                uint32_t a0 = ap0[0], a1 = ap1[0], a2 = ap0[4], a3 = ap1[4];
#pragma unroll
                for (int na = 0; na < 4; na++) {
                    mma_tf32(acc[ma][na][0], acc[ma][na][1], acc[ma][na][2], acc[ma][na][3],
                             a0, a1, a2, a3, bfr[na][0], bfr[na][1]);
                }
            }
        }
        __syncthreads();
    }

#pragma unroll
    for (int na = 0; na < 4; na++) {
        const int col = bn + warp_n * 32 + na * 8 + 2 * tig;
        float b0 = 0.f, b1 = 0.f;
        if (bias) { b0 = bias[col]; b1 = bias[col + 1]; }
#pragma unroll
        for (int ma = 0; ma < 4; ma++) {
            const int row = bm + warp_m * 64 + ma * 16 + grp;
            float2 v0 = make_float2(acc[ma][na][0] + b0, acc[ma][na][1] + b1);
            float2 v1 = make_float2(acc[ma][na][2] + b0, acc[ma][na][3] + b1);
            *(float2*)(Cm + (size_t)row * N + col) = v0;
            *(float2*)(Cm + (size_t)(row + 8) * N + col) = v1;
        }
    }
}

// ============== tensor-core flash attention (bf16x3, fp32-accurate) ==============
// grid (T/64, B*NH), 128 threads = 4 warps, warp owns 16 q-rows.
// smem: packed bf16x2 words, row stride AST=36 (frag loads conflict-free: bank=4*grp+tig).
#define AST 36
#define ATTN_SMEM_BYTES (6 * 64 * AST * 4)   // Qhi,Qlo,Khi,Klo,Vhi,Vlo = 55296 B

__global__ void __launch_bounds__(128) attn_mma(
    const float* __restrict__ QP, const float* __restrict__ KP,
    const float* __restrict__ VP, float* __restrict__ O)
{
    extern __shared__ uint32_t sm[];
    uint32_t* Qhi = sm;
    uint32_t* Qlo = sm + 1 * 64 * AST;
    uint32_t* Khi = sm + 2 * 64 * AST;
    uint32_t* Klo = sm + 3 * 64 * AST;
    uint32_t* Vhi = sm + 4 * 64 * AST;
    uint32_t* Vlo = sm + 5 * 64 * AST;

    const int bh = blockIdx.y;
    const int b  = bh >> 5;
    const int h  = bh & 31;
    const int g  = h & 7;
    const int q0 = blockIdx.x * 64;

    const float* Qg = QP + ((size_t)b * TT + q0) * CC + h * HD;
    const float* Kg = KP + (size_t)b * TT * (NG * HD) + g * HD;
    const float* Vg = VP + (size_t)b * TT * (NG * HD) + g * HD;

    const int tid  = threadIdx.x;
    const int wid  = tid >> 5;
    const int lane = tid & 31;
    const int grp  = lane >> 2;   // 0..7
    const int tig  = lane & 3;    // 0..3
    const int m0   = wid * 16;    // warp's q-row base

    // ---- load + pack Q (scaled by 1/8), hi/lo split ----
#pragma unroll
    for (int it = 0; it < 8; it++) {
        int idx = tid + it * 128;
        int r = idx >> 4, c4 = idx & 15;
        float4 v = *(const float4*)(Qg + (size_t)r * CC + c4 * 4);
        v.x *= 0.125f; v.y *= 0.125f; v.z *= 0.125f; v.w *= 0.125f;
        uint32_t h0, l0, h1, l1;
        split2(v.x, v.y, h0, l0);
        split2(v.z, v.w, h1, l1);
        Qhi[r * AST + 2 * c4 + 0] = h0;  Qhi[r * AST + 2 * c4 + 1] = h1;
        Qlo[r * AST + 2 * c4 + 0] = l0;  Qlo[r * AST + 2 * c4 + 1] = l1;
    }
    __syncthreads();

    // ---- hoist Q A-fragments for the whole kv loop ----
    uint32_t qa_h[4][4], qa_l[4][4];
#pragma unroll
    for (int c = 0; c < 4; c++) {
        int w0 = 8 * c + tig;
        qa_h[c][0] = Qhi[(m0 + grp) * AST + w0];
        qa_h[c][1] = Qhi[(m0 + grp + 8) * AST + w0];
        qa_h[c][2] = Qhi[(m0 + grp) * AST + w0 + 4];
        qa_h[c][3] = Qhi[(m0 + grp + 8) * AST + w0 + 4];
        qa_l[c][0] = Qlo[(m0 + grp) * AST + w0];
        qa_l[c][1] = Qlo[(m0 + grp + 8) * AST + w0];
        qa_l[c][2] = Qlo[(m0 + grp) * AST + w0 + 4];
        qa_l[c][3] = Qlo[(m0 + grp + 8) * AST + w0 + 4];
    }

    float oacc[8][4];
#pragma unroll
    for (int i = 0; i < 8; i++)
#pragma unroll
        for (int j = 0; j < 4; j++) oacc[i][j] = 0.f;
    float m_r0 = -INFINITY, m_r1 = -INFINITY, l_r0 = 0.f, l_r1 = 0.f;

    for (int kv = 0; kv < TT; kv += 64) {
        // ---- gmem loads (coalesced float4) ----
        float4 kreg[8];
#pragma unroll
        for (int it = 0; it < 8; it++) {
            int idx = tid + it * 128;
            int r = idx >> 4, c4 = idx & 15;
            kreg[it] = *(const float4*)(Kg + (size_t)(kv + r) * (NG * HD) + c4 * 4);
        }
        float4 va[4], vb[4];
#pragma unroll
        for (int it = 0; it < 4; it++) {
            int idx = tid + it * 128;
            int rp = idx >> 4, c4 = idx & 15;
            va[it] = *(const float4*)(Vg + (size_t)(kv + 2 * rp) * (NG * HD) + c4 * 4);
            vb[it] = *(const float4*)(Vg + (size_t)(kv + 2 * rp + 1) * (NG * HD) + c4 * 4);
        }
        __syncthreads();   // previous iteration's K/V reads done

        // ---- pack K: word (kv row r, hd pair) ----
#pragma unroll
        for (int it = 0; it < 8; it++) {
            int idx = tid + it * 128;
            int r = idx >> 4, c4 = idx & 15;
            uint32_t h0, l0, h1, l1;
            split2(kreg[it].x, kreg[it].y, h0, l0);
            split2(kreg[it].z, kreg[it].w, h1, l1);
            Khi[r * AST + 2 * c4 + 0] = h0;  Khi[r * AST + 2 * c4 + 1] = h1;
            Klo[r * AST + 2 * c4 + 0] = l0;  Klo[r * AST + 2 * c4 + 1] = l1;
        }
        // ---- pack V transposed: word (hd row, kv pair) ----
#pragma unroll
        for (int it = 0; it < 4; it++) {
            int idx = tid + it * 128;
            int rp = idx >> 4, c4 = idx & 15;
            float av[4] = {va[it].x, va[it].y, va[it].z, va[it].w};
            float bv[4] = {vb[it].x, vb[it].y, vb[it].z, vb[it].w};
#pragma unroll
            for (int j = 0; j < 4; j++) {
                uint32_t hw, lw;
                split2(av[j], bv[j], hw, lw);
                Vhi[(4 * c4 + j) * AST + rp] = hw;
                Vlo[(4 * c4 + j) * AST + rp] = lw;
            }
        }
        __syncthreads();

        // ---- S = Q @ K^T  (8 n-atoms x 4 k-chunks x 3 terms) ----
        float sacc[8][4];
#pragma unroll
        for (int i = 0; i < 8; i++)
#pragma unroll
            for (int j = 0; j < 4; j++) sacc[i][j] = 0.f;
#pragma unroll
        for (int c = 0; c < 4; c++) {
#pragma unroll
            for (int gg = 0; gg < 8; gg++) {
                const int rowk = (8 * gg + grp) * AST + 8 * c + tig;
                uint32_t bh0 = Khi[rowk], bh1 = Khi[rowk + 4];
                uint32_t bl0 = Klo[rowk], bl1 = Klo[rowk + 4];
                mma_bf16(sacc[gg], qa_h[c][0], qa_h[c][1], qa_h[c][2], qa_h[c][3], bh0, bh1);
                mma_bf16(sacc[gg], qa_h[c][0], qa_h[c][1], qa_h[c][2], qa_h[c][3], bl0, bl1);
                mma_bf16(sacc[gg], qa_l[c][0], qa_l[c][1], qa_l[c][2], qa_l[c][3], bh0, bh1);
            }
        }

        // ---- online softmax (rows grp and grp+8; reduce across quad) ----
        float rm0 = -INFINITY, rm1 = -INFINITY;
#pragma unroll
        for (int gg = 0; gg < 8; gg++) {
            rm0 = fmaxf(rm0, fmaxf(sacc[gg][0], sacc[gg][1]));
            rm1 = fmaxf(rm1, fmaxf(sacc[gg][2], sacc[gg][3]));
        }
        rm0 = fmaxf(rm0, __shfl_xor_sync(0xffffffffu, rm0, 1));
        rm0 = fmaxf(rm0, __shfl_xor_sync(0xffffffffu, rm0, 2));
        rm1 = fmaxf(rm1, __shfl_xor_sync(0xffffffffu, rm1, 1));
        rm1 = fmaxf(rm1, __shfl_xor_sync(0xffffffffu, rm1, 2));

        float nm0 = fmaxf(m_r0, rm0), nm1 = fmaxf(m_r1, rm1);
        float sc0 = __expf(m_r0 - nm0), sc1 = __expf(m_r1 - nm1);
        m_r0 = nm0; m_r1 = nm1;

        float rs0 = 0.f, rs1 = 0.f;
#pragma unroll
        for (int gg = 0; gg < 8; gg++) {
            sacc[gg][0] = __expf(sacc[gg][0] - nm0);
            sacc[gg][1] = __expf(sacc[gg][1] - nm0);
            sacc[gg][2] = __expf(sacc[gg][2] - nm1);
            sacc[gg][3] = __expf(sacc[gg][3] - nm1);
            rs0 += sacc[gg][0] + sacc[gg][1];
            rs1 += sacc[gg][2] + sacc[gg][3];
        }
        rs0 += __shfl_xor_sync(0xffffffffu, rs0, 1);
        rs0 += __shfl_xor_sync(0xffffffffu, rs0, 2);
        rs1 += __shfl_xor_sync(0xffffffffu, rs1, 1);
        rs1 += __shfl_xor_sync(0xffffffffu, rs1, 2);
        l_r0 = l_r0 * sc0 + rs0;
        l_r1 = l_r1 * sc1 + rs1;
#pragma unroll
        for (int i = 0; i < 8; i++) {
            oacc[i][0] *= sc0; oacc[i][1] *= sc0;
            oacc[i][2] *= sc1; oacc[i][3] *= sc1;
        }

        // ---- pack P hi/lo (C-frag layout == A-frag layout for PV) ----
        uint32_t phi[8][2], plo[8][2];
#pragma unroll
        for (int gg = 0; gg < 8; gg++) {
            split2(sacc[gg][0], sacc[gg][1], phi[gg][0], plo[gg][0]);
            split2(sacc[gg][2], sacc[gg][3], phi[gg][1], plo[gg][1]);
        }

        // ---- O += P @ V  (8 hd-atoms x 4 k-chunks x 3 terms) ----
#pragma unroll
        for (int c = 0; c < 4; c++) {
            uint32_t ah0 = phi[2 * c][0],     ah1 = phi[2 * c][1];
            uint32_t ah2 = phi[2 * c + 1][0], ah3 = phi[2 * c + 1][1];
            uint32_t al0 = plo[2 * c][0],     al1 = plo[2 * c][1];
            uint32_t al2 = plo[2 * c + 1][0], al3 = plo[2 * c + 1][1];
#pragma unroll
            for (int hh = 0; hh < 8; hh++) {
                const int rowv = (8 * hh + grp) * AST + 8 * c + tig;
                uint32_t bh0 = Vhi[rowv], bh1 = Vhi[rowv + 4];
                uint32_t bl0 = Vlo[rowv], bl1 = Vlo[rowv + 4];
                mma_bf16(oacc[hh], ah0, ah1, ah2, ah3, bh0, bh1);
                mma_bf16(oacc[hh], ah0, ah1, ah2, ah3, bl0, bl1);
                mma_bf16(oacc[hh], al0, al1, al2, al3, bh0, bh1);
            }
        }
    }

    // ---- normalize + store ----
    const float inv0 = 1.0f / l_r0, inv1 = 1.0f / l_r1;
    float* Og = O + ((size_t)b * TT + q0) * CC + h * HD;
    const int r0 = m0 + grp, r1 = m0 + grp + 8;
#pragma unroll
    for (int hh = 0; hh < 8; hh++) {
        const int col = 8 * hh + 2 * tig;
        *(float2*)(Og + (size_t)r0 * CC + col) = make_float2(oacc[hh][0] * inv0, oacc[hh][1] * inv0);
        *(float2*)(Og + (size_t)r1 * CC + col) = make_float2(oacc[hh][2] * inv1, oacc[hh][3] * inv1);
    }
}

// ---------------- launch ----------------
extern "C" void kernel_launch(void* const* d_in, const int* in_sizes, int n_in,
                              void* d_out, int out_size)
{
    const float* q  = (const float*)d_in[0];
    const float* k  = (const float*)d_in[1];
    const float* v  = (const float*)d_in[2];
    const float* Wq = (const float*)d_in[3];
    const float* Wk = (const float*)d_in[4];
    const float* Wv = (const float*)d_in[5];
    const float* Wp = (const float*)d_in[6];
    const float* bp = (const float*)d_in[7];
    float* out = (float*)d_out;

    float *pQP, *pKP, *pVP, *pO;
    cudaGetSymbolAddress((void**)&pQP, g_QP);
    cudaGetSymbolAddress((void**)&pKP, g_KP);
    cudaGetSymbolAddress((void**)&pVP, g_VP);
    cudaGetSymbolAddress((void**)&pO,  g_O);

    cudaFuncSetAttribute(gemm_nt_mma, cudaFuncAttributeMaxDynamicSharedMemorySize, GEMM_SMEM_BYTES);
    cudaFuncSetAttribute(attn_mma, cudaFuncAttributeMaxDynamicSharedMemorySize, ATTN_SMEM_BYTES);

    const int M = BB * TT;  // 4096

    // projections (tf32 mma.sync)
    gemm_nt_mma<<<dim3(CC / 128, M / 128), 256, GEMM_SMEM_BYTES>>>(q, Wq, nullptr, pQP, M, CC, CC);
    gemm_nt_mma<<<dim3((NG * HD) / 128, M / 128), 256, GEMM_SMEM_BYTES>>>(k, Wk, nullptr, pKP, M, NG * HD, CC);
    gemm_nt_mma<<<dim3((NG * HD) / 128, M / 128), 256, GEMM_SMEM_BYTES>>>(v, Wv, nullptr, pVP, M, NG * HD, CC);

    // attention (bf16x3 tensor-core flash attention)
    attn_mma<<<dim3(TT / 64, BB * NH), 128, ATTN_SMEM_BYTES>>>(pQP, pKP, pVP, pO);

    // output projection + bias (tf32 mma.sync)
    gemm_nt_mma<<<dim3(CC / 128, M / 128), 256, GEMM_SMEM_BYTES>>>(pO, Wp, bp, out, M, CC, CC);
}

// round 5
// speedup vs baseline: 3.1028x; 1.0275x over previous
#include <cuda_runtime.h>
#include <cuda_bf16.h>
#include <cstdint>
#include <math.h>

#define BB 2
#define TT 2048
#define CC 2048
#define NH 32
#define NG 8
#define HD 64

// ---------------- scratch (no allocations allowed) ----------------
__device__ float g_QP[BB * TT * CC];        // Q projection out
__device__ float g_KP[BB * TT * NG * HD];   // K projection out
__device__ float g_VP[BB * TT * NG * HD];   // V projection out
__device__ float g_O [BB * TT * CC];        // attention out (converted in-place to tf32 before out-proj)
// tf32-rounded copies of GEMM operands
__device__ float g_qc[BB * TT * CC];
__device__ float g_kc[BB * TT * CC];
__device__ float g_vc[BB * TT * CC];
__device__ float g_wq[CC * CC];
__device__ float g_wk[NG * HD * CC];
__device__ float g_wv[NG * HD * CC];
__device__ float g_wp[CC * CC];

// ---------------- helpers ----------------
__device__ __forceinline__ uint32_t f2tf32(float x) {
    uint32_t r;
    asm("cvt.rna.tf32.f32 %0, %1;" : "=r"(r) : "f"(x));
    return r;
}
__device__ __forceinline__ void mma_tf32(float& d0, float& d1, float& d2, float& d3,
                                         uint32_t a0, uint32_t a1, uint32_t a2, uint32_t a3,
                                         uint32_t b0, uint32_t b1)
{
    asm volatile(
        "mma.sync.aligned.m16n8k8.row.col.f32.tf32.tf32.f32 "
        "{%0,%1,%2,%3}, {%4,%5,%6,%7}, {%8,%9}, {%0,%1,%2,%3};"
        : "+f"(d0), "+f"(d1), "+f"(d2), "+f"(d3)
        : "r"(a0), "r"(a1), "r"(a2), "r"(a3), "r"(b0), "r"(b1));
}
__device__ __forceinline__ void mma_bf16(float* d,
                                         uint32_t a0, uint32_t a1, uint32_t a2, uint32_t a3,
                                         uint32_t b0, uint32_t b1)
{
    asm volatile(
        "mma.sync.aligned.m16n8k16.row.col.f32.bf16.bf16.f32 "
        "{%0,%1,%2,%3}, {%4,%5,%6,%7}, {%8,%9}, {%0,%1,%2,%3};"
        : "+f"(d[0]), "+f"(d[1]), "+f"(d[2]), "+f"(d[3])
        : "r"(a0), "r"(a1), "r"(a2), "r"(a3), "r"(b0), "r"(b1));
}
__device__ __forceinline__ uint32_t packbf2(float a, float b) {
    __nv_bfloat162 t = __floats2bfloat162_rn(a, b);
    return *(uint32_t*)&t;
}
__device__ __forceinline__ void split2(float a, float b, uint32_t& hi, uint32_t& lo) {
    __nv_bfloat16 ah = __float2bfloat16_rn(a);
    __nv_bfloat16 bh = __float2bfloat16_rn(b);
    float ar = a - __bfloat162float(ah);
    float br = b - __bfloat162float(bh);
    __nv_bfloat162 h; h.x = ah; h.y = bh;
    hi = *(uint32_t*)&h;
    lo = packbf2(ar, br);
}
__device__ __forceinline__ uint32_t smem_u32(const void* p) {
    uint32_t a;
    asm("{ .reg .u64 t; cvta.to.shared.u64 t, %1; cvt.u32.u64 %0, t; }" : "=r"(a) : "l"(p));
    return a;
}
__device__ __forceinline__ void cp16(uint32_t dst, const void* src) {
    asm volatile("cp.async.ca.shared.global [%0], [%1], 16;" :: "r"(dst), "l"(src));
}
__device__ __forceinline__ void cp_commit() { asm volatile("cp.async.commit_group;" ::: "memory"); }
template<int N> __device__ __forceinline__ void cp_wait() {
    asm volatile("cp.async.wait_group %0;" :: "n"(N) : "memory");
}

// ---------------- tf32 conversion (elementwise) ----------------
__global__ void __launch_bounds__(256) conv_tf32(const float* __restrict__ s,
                                                 float* __restrict__ d, int n4)
{
    int i = blockIdx.x * 256 + threadIdx.x;
    if (i >= n4) return;
    float4 v = ((const float4*)s)[i];
    v.x = __uint_as_float(f2tf32(v.x));
    v.y = __uint_as_float(f2tf32(v.y));
    v.z = __uint_as_float(f2tf32(v.z));
    v.w = __uint_as_float(f2tf32(v.w));
    ((float4*)d)[i] = v;
}

// ============== cp.async tf32 GEMM: C[m][n] = sum_k A[m][k]*B[n][k] (+bias) ==============
// inputs MUST already be tf32-rounded. 128x128 tile, BK=16, 4-stage cp.async ring.
#define GST 20
#define STGF (2 * 128 * GST)                  // floats per stage (A slab + B slab)
#define GEMM_SMEM_BYTES (4 * STGF * 4)        // 81920

__device__ __forceinline__ void gemm_body(
    const float* __restrict__ A, const float* __restrict__ Bm,
    const float* __restrict__ bias, float* __restrict__ Cm,
    int N, int K, int bm, int bn)
{
    extern __shared__ float smem[];
    const uint32_t smb = smem_u32(smem);

    const int tid  = threadIdx.x;
    const int wid  = tid >> 5;
    const int lane = tid & 31;
    const int grp  = lane >> 2;
    const int tig  = lane & 3;
    const int warp_m = wid >> 2;
    const int warp_n = wid & 3;

    const int srow = tid >> 2;
    const int scg  = (tid & 3) * 4;
    const float* Ag = A  + (size_t)(bm + srow) * K + scg;
    const float* Bg = Bm + (size_t)(bn + srow) * K + scg;
    const uint32_t a_dst = smb + (uint32_t)(srow * GST + scg) * 4;
    const uint32_t HALF  = (uint32_t)(64 * GST) * 4;
    const uint32_t BOFF  = (uint32_t)(128 * GST) * 4;

    float acc[4][4][4];
#pragma unroll
    for (int i = 0; i < 4; i++)
#pragma unroll
        for (int j = 0; j < 4; j++)
#pragma unroll
            for (int r = 0; r < 4; r++) acc[i][j][r] = 0.f;

    const int NSTAGE = K / 16;

#define GEMM_ISSUE(sl, it) do {                                      \
        const int _k0 = (it) * 16;                                   \
        const uint32_t _ab = a_dst + (uint32_t)(sl) * (STGF * 4);    \
        cp16(_ab,               Ag + _k0);                           \
        cp16(_ab + HALF,        Ag + 64 * (size_t)K + _k0);          \
        cp16(_ab + BOFF,        Bg + _k0);                           \
        cp16(_ab + BOFF + HALF, Bg + 64 * (size_t)K + _k0);          \
    } while (0)

    GEMM_ISSUE(0, 0); cp_commit();
    GEMM_ISSUE(1, 1); cp_commit();
    GEMM_ISSUE(2, 2); cp_commit();

    for (int it = 0; it < NSTAGE; it++) {
        cp_wait<2>();
        __syncthreads();
        if (it + 3 < NSTAGE) { GEMM_ISSUE((it + 3) & 3, it + 3); }
        cp_commit();

        const float* Asb = smem + (it & 3) * STGF;
        const float* Bsb = Asb + 128 * GST;
#pragma unroll
        for (int kk = 0; kk < 16; kk += 8) {
            uint32_t bfr[4][2];
#pragma unroll
            for (int na = 0; na < 4; na++) {
                const uint32_t* bp = (const uint32_t*)(Bsb + (warp_n * 32 + na * 8 + grp) * GST + kk + tig);
                bfr[na][0] = bp[0];
                bfr[na][1] = bp[4];
            }
#pragma unroll
            for (int ma = 0; ma < 4; ma++) {
                const uint32_t* ap0 = (const uint32_t*)(Asb + (warp_m * 64 + ma * 16 + grp) * GST + kk + tig);
                const uint32_t* ap1 = (const uint32_t*)(Asb + (warp_m * 64 + ma * 16 + 8 + grp) * GST + kk + tig);
                uint32_t a0 = ap0[0], a1 = ap1[0], a2 = ap0[4], a3 = ap1[4];
#pragma unroll
                for (int na = 0; na < 4; na++) {
                    mma_tf32(acc[ma][na][0], acc[ma][na][1], acc[ma][na][2], acc[ma][na][3],
                             a0, a1, a2, a3, bfr[na][0], bfr[na][1]);
                }
            }
        }
    }
#undef GEMM_ISSUE

#pragma unroll
    for (int na = 0; na < 4; na++) {
        const int col = bn + warp_n * 32 + na * 8 + 2 * tig;
        float b0 = 0.f, b1 = 0.f;
        if (bias) { b0 = bias[col]; b1 = bias[col + 1]; }
#pragma unroll
        for (int ma = 0; ma < 4; ma++) {
            const int row = bm + warp_m * 64 + ma * 16 + grp;
            float2 v0 = make_float2(acc[ma][na][0] + b0, acc[ma][na][1] + b1);
            float2 v1 = make_float2(acc[ma][na][2] + b0, acc[ma][na][3] + b1);
            *(float2*)(Cm + (size_t)row * N + col) = v0;
            *(float2*)(Cm + (size_t)(row + 8) * N + col) = v1;
        }
    }
}

__global__ void __launch_bounds__(256, 2) gemm_tc(
    const float* __restrict__ A, const float* __restrict__ Bm,
    const float* __restrict__ bias, float* __restrict__ Cm, int N, int K)
{
    gemm_body(A, Bm, bias, Cm, N, K, blockIdx.y * 128, blockIdx.x * 128);
}

// fused K+V projections: blockIdx.x 0..3 -> K proj, 4..7 -> V proj
__global__ void __launch_bounds__(256, 2) gemm_kv(
    const float* __restrict__ kc, const float* __restrict__ vc,
    const float* __restrict__ wk, const float* __restrict__ wv,
    float* __restrict__ KP, float* __restrict__ VP)
{
    const bool isV = blockIdx.x >= 4;
    gemm_body(isV ? vc : kc, isV ? wv : wk, nullptr, isV ? VP : KP,
              NG * HD, CC, blockIdx.y * 128, (blockIdx.x & 3) * 128);
}

// ============== tensor-core flash attention (bf16x3), 8 warps, 128 q-rows/block ==============
#define AST 36
#define ATTN_SMEM_BYTES ((2 * 128 * AST + 4 * 64 * AST) * 4)   // 73728

__global__ void __launch_bounds__(256, 1) attn_mma(
    const float* __restrict__ QP, const float* __restrict__ KP,
    const float* __restrict__ VP, float* __restrict__ O)
{
    extern __shared__ uint32_t sm[];
    uint32_t* Qhi = sm;
    uint32_t* Qlo = sm + 128 * AST;
    uint32_t* Khi = sm + 2 * 128 * AST;
    uint32_t* Klo = Khi + 64 * AST;
    uint32_t* Vhi = Klo + 64 * AST;
    uint32_t* Vlo = Vhi + 64 * AST;

    const int bh = blockIdx.y;
    const int b  = bh >> 5;
    const int h  = bh & 31;
    const int g  = h & 7;
    const int q0 = blockIdx.x * 128;

    const float* Qg = QP + ((size_t)b * TT + q0) * CC + h * HD;
    const float* Kg = KP + (size_t)b * TT * (NG * HD) + g * HD;
    const float* Vg = VP + (size_t)b * TT * (NG * HD) + g * HD;

    const int tid  = threadIdx.x;
    const int wid  = tid >> 5;     // 0..7
    const int lane = tid & 31;
    const int grp  = lane >> 2;
    const int tig  = lane & 3;
    const int m0   = wid * 16;     // warp's q-row base (0..112)

    // ---- load + pack Q (scaled), hi/lo split: 128 rows ----
#pragma unroll
    for (int it = 0; it < 8; it++) {
        int idx = tid + it * 256;
        int r = idx >> 4, c4 = idx & 15;
        float4 v = *(const float4*)(Qg + (size_t)r * CC + c4 * 4);
        v.x *= 0.125f; v.y *= 0.125f; v.z *= 0.125f; v.w *= 0.125f;
        uint32_t h0, l0, h1, l1;
        split2(v.x, v.y, h0, l0);
        split2(v.z, v.w, h1, l1);
        Qhi[r * AST + 2 * c4 + 0] = h0;  Qhi[r * AST + 2 * c4 + 1] = h1;
        Qlo[r * AST + 2 * c4 + 0] = l0;  Qlo[r * AST + 2 * c4 + 1] = l1;
    }
    __syncthreads();

    // ---- hoist Q A-fragments ----
    uint32_t qa_h[4][4], qa_l[4][4];
#pragma unroll
    for (int c = 0; c < 4; c++) {
        int w0 = 8 * c + tig;
        qa_h[c][0] = Qhi[(m0 + grp) * AST + w0];
        qa_h[c][1] = Qhi[(m0 + grp + 8) * AST + w0];
        qa_h[c][2] = Qhi[(m0 + grp) * AST + w0 + 4];
        qa_h[c][3] = Qhi[(m0 + grp + 8) * AST + w0 + 4];
        qa_l[c][0] = Qlo[(m0 + grp) * AST + w0];
        qa_l[c][1] = Qlo[(m0 + grp + 8) * AST + w0];
        qa_l[c][2] = Qlo[(m0 + grp) * AST + w0 + 4];
        qa_l[c][3] = Qlo[(m0 + grp + 8) * AST + w0 + 4];
    }

    float oacc[8][4];
#pragma unroll
    for (int i = 0; i < 8; i++)
#pragma unroll
        for (int j = 0; j < 4; j++) oacc[i][j] = 0.f;
    float m_r0 = -INFINITY, m_r1 = -INFINITY, l_r0 = 0.f, l_r1 = 0.f;

    // ---- prologue loads for tile 0 ----
    float4 kreg[4], va[2], vb[2];
#pragma unroll
    for (int it = 0; it < 4; it++) {
        int idx = tid + it * 256;
        int r = idx >> 4, c4 = idx & 15;
        kreg[it] = *(const float4*)(Kg + (size_t)r * (NG * HD) + c4 * 4);
    }
#pragma unroll
    for (int it = 0; it < 2; it++) {
        int idx = tid + it * 256;
        int rp = idx >> 4, c4 = idx & 15;
        va[it] = *(const float4*)(Vg + (size_t)(2 * rp) * (NG * HD) + c4 * 4);
        vb[it] = *(const float4*)(Vg + (size_t)(2 * rp + 1) * (NG * HD) + c4 * 4);
    }

    for (int kv = 0; kv < TT; kv += 64) {
        __syncthreads();   // all warps done with previous tile's K/V smem

        // ---- pack K ----
#pragma unroll
        for (int it = 0; it < 4; it++) {
            int idx = tid + it * 256;
            int r = idx >> 4, c4 = idx & 15;
            uint32_t h0, l0, h1, l1;
            split2(kreg[it].x, kreg[it].y, h0, l0);
            split2(kreg[it].z, kreg[it].w, h1, l1);
            Khi[r * AST + 2 * c4 + 0] = h0;  Khi[r * AST + 2 * c4 + 1] = h1;
            Klo[r * AST + 2 * c4 + 0] = l0;  Klo[r * AST + 2 * c4 + 1] = l1;
        }
        // ---- pack V transposed ----
#pragma unroll
        for (int it = 0; it < 2; it++) {
            int idx = tid + it * 256;
            int rp = idx >> 4, c4 = idx & 15;
            float av[4] = {va[it].x, va[it].y, va[it].z, va[it].w};
            float bv[4] = {vb[it].x, vb[it].y, vb[it].z, vb[it].w};
#pragma unroll
            for (int j = 0; j < 4; j++) {
                uint32_t hw, lw;
                split2(av[j], bv[j], hw, lw);
                Vhi[(4 * c4 + j) * AST + rp] = hw;
                Vlo[(4 * c4 + j) * AST + rp] = lw;
            }
        }

        // ---- prefetch next tile's K/V (lands during MMA/softmax) ----
        if (kv + 64 < TT) {
            const float* Kn = Kg + (size_t)(kv + 64) * (NG * HD);
            const float* Vn = Vg + (size_t)(kv + 64) * (NG * HD);
#pragma unroll
            for (int it = 0; it < 4; it++) {
                int idx = tid + it * 256;
                int r = idx >> 4, c4 = idx & 15;
                kreg[it] = *(const float4*)(Kn + (size_t)r * (NG * HD) + c4 * 4);
            }
#pragma unroll
            for (int it = 0; it < 2; it++) {
                int idx = tid + it * 256;
                int rp = idx >> 4, c4 = idx & 15;
                va[it] = *(const float4*)(Vn + (size_t)(2 * rp) * (NG * HD) + c4 * 4);
                vb[it] = *(const float4*)(Vn + (size_t)(2 * rp + 1) * (NG * HD) + c4 * 4);
            }
        }
        __syncthreads();   // packed tiles visible

        // ---- S = Q @ K^T ----
        float sacc[8][4];
#pragma unroll
        for (int i = 0; i < 8; i++)
#pragma unroll
            for (int j = 0; j < 4; j++) sacc[i][j] = 0.f;
#pragma unroll
        for (int c = 0; c < 4; c++) {
#pragma unroll
            for (int gg = 0; gg < 8; gg++) {
                const int rowk = (8 * gg + grp) * AST + 8 * c + tig;
                uint32_t bh0 = Khi[rowk], bh1 = Khi[rowk + 4];
                uint32_t bl0 = Klo[rowk], bl1 = Klo[rowk + 4];
                mma_bf16(sacc[gg], qa_h[c][0], qa_h[c][1], qa_h[c][2], qa_h[c][3], bh0, bh1);
                mma_bf16(sacc[gg], qa_h[c][0], qa_h[c][1], qa_h[c][2], qa_h[c][3], bl0, bl1);
                mma_bf16(sacc[gg], qa_l[c][0], qa_l[c][1], qa_l[c][2], qa_l[c][3], bh0, bh1);
            }
        }

        // ---- online softmax ----
        float rm0 = -INFINITY, rm1 = -INFINITY;
#pragma unroll
        for (int gg = 0; gg < 8; gg++) {
            rm0 = fmaxf(rm0, fmaxf(sacc[gg][0], sacc[gg][1]));
            rm1 = fmaxf(rm1, fmaxf(sacc[gg][2], sacc[gg][3]));
        }
        rm0 = fmaxf(rm0, __shfl_xor_sync(0xffffffffu, rm0, 1));
        rm0 = fmaxf(rm0, __shfl_xor_sync(0xffffffffu, rm0, 2));
        rm1 = fmaxf(rm1, __shfl_xor_sync(0xffffffffu, rm1, 1));
        rm1 = fmaxf(rm1, __shfl_xor_sync(0xffffffffu, rm1, 2));

        float nm0 = fmaxf(m_r0, rm0), nm1 = fmaxf(m_r1, rm1);
        float sc0 = __expf(m_r0 - nm0), sc1 = __expf(m_r1 - nm1);
        m_r0 = nm0; m_r1 = nm1;

        float rs0 = 0.f, rs1 = 0.f;
#pragma unroll
        for (int gg = 0; gg < 8; gg++) {
            sacc[gg][0] = __expf(sacc[gg][0] - nm0);
            sacc[gg][1] = __expf(sacc[gg][1] - nm0);
            sacc[gg][2] = __expf(sacc[gg][2] - nm1);
            sacc[gg][3] = __expf(sacc[gg][3] - nm1);
            rs0 += sacc[gg][0] + sacc[gg][1];
            rs1 += sacc[gg][2] + sacc[gg][3];
        }
        rs0 += __shfl_xor_sync(0xffffffffu, rs0, 1);
        rs0 += __shfl_xor_sync(0xffffffffu, rs0, 2);
        rs1 += __shfl_xor_sync(0xffffffffu, rs1, 1);
        rs1 += __shfl_xor_sync(0xffffffffu, rs1, 2);
        l_r0 = l_r0 * sc0 + rs0;
        l_r1 = l_r1 * sc1 + rs1;
#pragma unroll
        for (int i = 0; i < 8; i++) {
            oacc[i][0] *= sc0; oacc[i][1] *= sc0;
            oacc[i][2] *= sc1; oacc[i][3] *= sc1;
        }

        // ---- pack P hi/lo ----
        uint32_t phi[8][2], plo[8][2];
#pragma unroll
        for (int gg = 0; gg < 8; gg++) {
            split2(sacc[gg][0], sacc[gg][1], phi[gg][0], plo[gg][0]);
            split2(sacc[gg][2], sacc[gg][3], phi[gg][1], plo[gg][1]);
        }

        // ---- O += P @ V ----
#pragma unroll
        for (int c = 0; c < 4; c++) {
            uint32_t ah0 = phi[2 * c][0],     ah1 = phi[2 * c][1];
            uint32_t ah2 = phi[2 * c + 1][0], ah3 = phi[2 * c + 1][1];
            uint32_t al0 = plo[2 * c][0],     al1 = plo[2 * c][1];
            uint32_t al2 = plo[2 * c + 1][0], al3 = plo[2 * c + 1][1];
#pragma unroll
            for (int hh = 0; hh < 8; hh++) {
                const int rowv = (8 * hh + grp) * AST + 8 * c + tig;
                uint32_t bh0 = Vhi[rowv], bh1 = Vhi[rowv + 4];
                uint32_t bl0 = Vlo[rowv], bl1 = Vlo[rowv + 4];
                mma_bf16(oacc[hh], ah0, ah1, ah2, ah3, bh0, bh1);
                mma_bf16(oacc[hh], ah0, ah1, ah2, ah3, bl0, bl1);
                mma_bf16(oacc[hh], al0, al1, al2, al3, bh0, bh1);
            }
        }
    }

    // ---- normalize + store ----
    const float inv0 = 1.0f / l_r0, inv1 = 1.0f / l_r1;
    float* Og = O + ((size_t)b * TT + q0) * CC + h * HD;
    const int r0 = m0 + grp, r1 = m0 + grp + 8;
#pragma unroll
    for (int hh = 0; hh < 8; hh++) {
        const int col = 8 * hh + 2 * tig;
        *(float2*)(Og + (size_t)r0 * CC + col) = make_float2(oacc[hh][0] * inv0, oacc[hh][1] * inv0);
        *(float2*)(Og + (size_t)r1 * CC + col) = make_float2(oacc[hh][2] * inv1, oacc[hh][3] * inv1);
    }
}

// ---------------- launch ----------------
extern "C" void kernel_launch(void* const* d_in, const int* in_sizes, int n_in,
                              void* d_out, int out_size)
{
    const float* q  = (const float*)d_in[0];
    const float* k  = (const float*)d_in[1];
    const float* v  = (const float*)d_in[2];
    const float* Wq = (const float*)d_in[3];
    const float* Wk = (const float*)d_in[4];
    const float* Wv = (const float*)d_in[5];
    const float* Wp = (const float*)d_in[6];
    const float* bp = (const float*)d_in[7];
    float* out = (float*)d_out;

    float *pQP, *pKP, *pVP, *pO, *pqc, *pkc, *pvc, *pwq, *pwk, *pwv, *pwp;
    cudaGetSymbolAddress((void**)&pQP, g_QP);
    cudaGetSymbolAddress((void**)&pKP, g_KP);
    cudaGetSymbolAddress((void**)&pVP, g_VP);
    cudaGetSymbolAddress((void**)&pO,  g_O);
    cudaGetSymbolAddress((void**)&pqc, g_qc);
    cudaGetSymbolAddress((void**)&pkc, g_kc);
    cudaGetSymbolAddress((void**)&pvc, g_vc);
    cudaGetSymbolAddress((void**)&pwq, g_wq);
    cudaGetSymbolAddress((void**)&pwk, g_wk);
    cudaGetSymbolAddress((void**)&pwv, g_wv);
    cudaGetSymbolAddress((void**)&pwp, g_wp);

    cudaFuncSetAttribute(gemm_tc, cudaFuncAttributeMaxDynamicSharedMemorySize, GEMM_SMEM_BYTES);
    cudaFuncSetAttribute(gemm_kv, cudaFuncAttributeMaxDynamicSharedMemorySize, GEMM_SMEM_BYTES);
    cudaFuncSetAttribute(attn_mma, cudaFuncAttributeMaxDynamicSharedMemorySize, ATTN_SMEM_BYTES);

    const int M = BB * TT;  // 4096
    const int NBIG = M * CC / 4;       // 2097152 float4
    const int NWQ  = CC * CC / 4;      // 1048576
    const int NWK  = NG * HD * CC / 4; // 262144

    // tf32 pre-conversion
    conv_tf32<<<(NBIG + 255) / 256, 256>>>(q, pqc, NBIG);
    conv_tf32<<<(NBIG + 255) / 256, 256>>>(k, pkc, NBIG);
    conv_tf32<<<(NBIG + 255) / 256, 256>>>(v, pvc, NBIG);
    conv_tf32<<<(NWQ + 255) / 256, 256>>>(Wq, pwq, NWQ);
    conv_tf32<<<(NWK + 255) / 256, 256>>>(Wk, pwk, NWK);
    conv_tf32<<<(NWK + 255) / 256, 256>>>(Wv, pwv, NWK);
    conv_tf32<<<(NWQ + 255) / 256, 256>>>(Wp, pwp, NWQ);

    // projections
    gemm_tc<<<dim3(CC / 128, M / 128), 256, GEMM_SMEM_BYTES>>>(pqc, pwq, nullptr, pQP, CC, CC);
    gemm_kv<<<dim3(8, M / 128), 256, GEMM_SMEM_BYTES>>>(pkc, pvc, pwk, pwv, pKP, pVP);

    // attention (bf16x3, 128 q-rows/block)
    attn_mma<<<dim3(TT / 128, BB * NH), 256, ATTN_SMEM_BYTES>>>(pQP, pKP, pVP, pO);

    // convert attention output in-place, then output projection + bias
    conv_tf32<<<(NBIG + 255) / 256, 256>>>(pO, pO, NBIG);
    gemm_tc<<<dim3(CC / 128, M / 128), 256, GEMM_SMEM_BYTES>>>(pO, pwp, bp, out, CC, CC);
}

// round 6
// speedup vs baseline: 3.2747x; 1.0554x over previous
#include <cuda_runtime.h>
#include <cuda_bf16.h>
#include <cstdint>
#include <math.h>

#define BB 2
#define TT 2048
#define CC 2048
#define NH 32
#define NG 8
#define HD 64

// ---------------- scratch (no allocations allowed) ----------------
__device__ float g_QP[BB * TT * CC];
__device__ float g_KP[BB * TT * NG * HD];
__device__ float g_VP[BB * TT * NG * HD];
__device__ float g_O [BB * TT * CC];        // attn out, already tf32-rounded
__device__ float g_qc[BB * TT * CC];
__device__ float g_kc[BB * TT * CC];
__device__ float g_vc[BB * TT * CC];
__device__ float g_wq[CC * CC];
__device__ float g_wk[NG * HD * CC];
__device__ float g_wv[NG * HD * CC];
__device__ float g_wp[CC * CC];

// ---------------- helpers ----------------
__device__ __forceinline__ uint32_t f2tf32(float x) {
    uint32_t r;
    asm("cvt.rna.tf32.f32 %0, %1;" : "=r"(r) : "f"(x));
    return r;
}
__device__ __forceinline__ void mma_tf32(float& d0, float& d1, float& d2, float& d3,
                                         uint32_t a0, uint32_t a1, uint32_t a2, uint32_t a3,
                                         uint32_t b0, uint32_t b1)
{
    asm volatile(
        "mma.sync.aligned.m16n8k8.row.col.f32.tf32.tf32.f32 "
        "{%0,%1,%2,%3}, {%4,%5,%6,%7}, {%8,%9}, {%0,%1,%2,%3};"
        : "+f"(d0), "+f"(d1), "+f"(d2), "+f"(d3)
        : "r"(a0), "r"(a1), "r"(a2), "r"(a3), "r"(b0), "r"(b1));
}
__device__ __forceinline__ void mma_bf16(float* d,
                                         uint32_t a0, uint32_t a1, uint32_t a2, uint32_t a3,
                                         uint32_t b0, uint32_t b1)
{
    asm volatile(
        "mma.sync.aligned.m16n8k16.row.col.f32.bf16.bf16.f32 "
        "{%0,%1,%2,%3}, {%4,%5,%6,%7}, {%8,%9}, {%0,%1,%2,%3};"
        : "+f"(d[0]), "+f"(d[1]), "+f"(d[2]), "+f"(d[3])
        : "r"(a0), "r"(a1), "r"(a2), "r"(a3), "r"(b0), "r"(b1));
}
__device__ __forceinline__ uint32_t packbf2(float a, float b) {
    __nv_bfloat162 t = __floats2bfloat162_rn(a, b);
    return *(uint32_t*)&t;
}
__device__ __forceinline__ void split2(float a, float b, uint32_t& hi, uint32_t& lo) {
    __nv_bfloat16 ah = __float2bfloat16_rn(a);
    __nv_bfloat16 bh = __float2bfloat16_rn(b);
    float ar = a - __bfloat162float(ah);
    float br = b - __bfloat162float(bh);
    __nv_bfloat162 h; h.x = ah; h.y = bh;
    hi = *(uint32_t*)&h;
    lo = packbf2(ar, br);
}
__device__ __forceinline__ uint32_t smem_u32(const void* p) {
    uint32_t a;
    asm("{ .reg .u64 t; cvta.to.shared.u64 t, %1; cvt.u32.u64 %0, t; }" : "=r"(a) : "l"(p));
    return a;
}
__device__ __forceinline__ void cp16(uint32_t dst, const void* src) {
    asm volatile("cp.async.ca.shared.global [%0], [%1], 16;" :: "r"(dst), "l"(src));
}
__device__ __forceinline__ void cp_commit() { asm volatile("cp.async.commit_group;" ::: "memory"); }
template<int N> __device__ __forceinline__ void cp_wait() {
    asm volatile("cp.async.wait_group %0;" :: "n"(N) : "memory");
}

// ---------------- tf32 conversion (elementwise) ----------------
__global__ void __launch_bounds__(256) conv_tf32(const float* __restrict__ s,
                                                 float* __restrict__ d, int n4)
{
    int i = blockIdx.x * 256 + threadIdx.x;
    if (i >= n4) return;
    float4 v = ((const float4*)s)[i];
    v.x = __uint_as_float(f2tf32(v.x));
    v.y = __uint_as_float(f2tf32(v.y));
    v.z = __uint_as_float(f2tf32(v.z));
    v.w = __uint_as_float(f2tf32(v.w));
    ((float4*)d)[i] = v;
}

// ============== cp.async tf32 GEMM, 64-bit permuted fragment loads ==============
// inputs MUST be tf32-rounded. 128x128 tile, BK=16, 4-stage ring, GST=24 (8 mod 32 -> 64b conflict-free).
#define GST 24
#define STGF (2 * 128 * GST)                  // 6144 floats per stage
#define GEMM_SMEM_BYTES (4 * STGF * 4)        // 98304

__device__ __forceinline__ void gemm_body(
    const float* __restrict__ A, const float* __restrict__ Bm,
    const float* __restrict__ bias, float* __restrict__ Cm,
    int N, int K, int bm, int bn)
{
    extern __shared__ float smem[];
    const uint32_t smb = smem_u32(smem);

    const int tid  = threadIdx.x;
    const int wid  = tid >> 5;
    const int lane = tid & 31;
    const int grp  = lane >> 2;
    const int tig  = lane & 3;
    const int warp_m = wid >> 2;
    const int warp_n = wid & 3;

    const int srow = tid >> 2;
    const int scg  = (tid & 3) * 4;
    const float* Ag = A  + (size_t)(bm + srow) * K + scg;
    const float* Bg = Bm + (size_t)(bn + srow) * K + scg;
    const uint32_t a_dst = smb + (uint32_t)(srow * GST + scg) * 4;
    const uint32_t HALF  = (uint32_t)(64 * GST) * 4;
    const uint32_t BOFF  = (uint32_t)(128 * GST) * 4;

    float acc[4][4][4];
#pragma unroll
    for (int i = 0; i < 4; i++)
#pragma unroll
        for (int j = 0; j < 4; j++)
#pragma unroll
            for (int r = 0; r < 4; r++) acc[i][j][r] = 0.f;

    const int NSTAGE = K / 16;

#define GEMM_ISSUE(sl, it) do {                                      \
        const int _k0 = (it) * 16;                                   \
        const uint32_t _ab = a_dst + (uint32_t)(sl) * (STGF * 4);    \
        cp16(_ab,               Ag + _k0);                           \
        cp16(_ab + HALF,        Ag + 64 * (size_t)K + _k0);          \
        cp16(_ab + BOFF,        Bg + _k0);                           \
        cp16(_ab + BOFF + HALF, Bg + 64 * (size_t)K + _k0);          \
    } while (0)

    GEMM_ISSUE(0, 0); cp_commit();
    GEMM_ISSUE(1, 1); cp_commit();
    GEMM_ISSUE(2, 2); cp_commit();

    for (int it = 0; it < NSTAGE; it++) {
        cp_wait<2>();
        __syncthreads();
        if (it + 3 < NSTAGE) { GEMM_ISSUE((it + 3) & 3, it + 3); }
        cp_commit();

        const float* Asb = smem + (it & 3) * STGF;
        const float* Bsb = Asb + 128 * GST;
        // k-permuted 64-bit fragment loads: hw k slots (tig, tig+4) <- actual k (2tig, 2tig+1)
#pragma unroll
        for (int kk = 0; kk < 16; kk += 8) {
            uint2 bfr[4];
#pragma unroll
            for (int na = 0; na < 4; na++)
                bfr[na] = *(const uint2*)(Bsb + (warp_n * 32 + na * 8 + grp) * GST + kk + 2 * tig);
#pragma unroll
            for (int ma = 0; ma < 4; ma++) {
                uint2 av0 = *(const uint2*)(Asb + (warp_m * 64 + ma * 16 + grp) * GST + kk + 2 * tig);
                uint2 av1 = *(const uint2*)(Asb + (warp_m * 64 + ma * 16 + 8 + grp) * GST + kk + 2 * tig);
#pragma unroll
                for (int na = 0; na < 4; na++) {
                    mma_tf32(acc[ma][na][0], acc[ma][na][1], acc[ma][na][2], acc[ma][na][3],
                             av0.x, av1.x, av0.y, av1.y, bfr[na].x, bfr[na].y);
                }
            }
        }
    }
#undef GEMM_ISSUE

#pragma unroll
    for (int na = 0; na < 4; na++) {
        const int col = bn + warp_n * 32 + na * 8 + 2 * tig;
        float b0 = 0.f, b1 = 0.f;
        if (bias) { b0 = bias[col]; b1 = bias[col + 1]; }
#pragma unroll
        for (int ma = 0; ma < 4; ma++) {
            const int row = bm + warp_m * 64 + ma * 16 + grp;
            float2 v0 = make_float2(acc[ma][na][0] + b0, acc[ma][na][1] + b1);
            float2 v1 = make_float2(acc[ma][na][2] + b0, acc[ma][na][3] + b1);
            *(float2*)(Cm + (size_t)row * N + col) = v0;
            *(float2*)(Cm + (size_t)(row + 8) * N + col) = v1;
        }
    }
}

__global__ void __launch_bounds__(256, 2) gemm_tc(
    const float* __restrict__ A, const float* __restrict__ Bm,
    const float* __restrict__ bias, float* __restrict__ Cm, int N, int K)
{
    gemm_body(A, Bm, bias, Cm, N, K, blockIdx.y * 128, blockIdx.x * 128);
}

__global__ void __launch_bounds__(256, 2) gemm_kv(
    const float* __restrict__ kc, const float* __restrict__ vc,
    const float* __restrict__ wk, const float* __restrict__ wv,
    float* __restrict__ KP, float* __restrict__ VP)
{
    const bool isV = blockIdx.x >= 4;
    gemm_body(isV ? vc : kc, isV ? wv : wk, nullptr, isV ? VP : KP,
              NG * HD, CC, blockIdx.y * 128, (blockIdx.x & 3) * 128);
}

// ============== tensor-core flash attention (bf16x3), 64-bit Q/K frag loads ==============
// Q/K arrays stride 40 words (8 mod 32 -> conflict-free 64b); V arrays stride 36 (scalar path).
#define QKST 40
#define VST  36
#define ATTN_SMEM_BYTES ((2 * 128 * QKST + 2 * 64 * QKST + 2 * 64 * VST) * 4)  // 79872

__global__ void __launch_bounds__(256, 1) attn_mma(
    const float* __restrict__ QP, const float* __restrict__ KP,
    const float* __restrict__ VP, float* __restrict__ O)
{
    extern __shared__ uint32_t sm[];
    uint32_t* Qhi = sm;
    uint32_t* Qlo = Qhi + 128 * QKST;
    uint32_t* Khi = Qlo + 128 * QKST;
    uint32_t* Klo = Khi + 64 * QKST;
    uint32_t* Vhi = Klo + 64 * QKST;
    uint32_t* Vlo = Vhi + 64 * VST;

    const int bh = blockIdx.y;
    const int b  = bh >> 5;
    const int h  = bh & 31;
    const int g  = h & 7;
    const int q0 = blockIdx.x * 128;

    const float* Qg = QP + ((size_t)b * TT + q0) * CC + h * HD;
    const float* Kg = KP + (size_t)b * TT * (NG * HD) + g * HD;
    const float* Vg = VP + (size_t)b * TT * (NG * HD) + g * HD;

    const int tid  = threadIdx.x;
    const int wid  = tid >> 5;
    const int lane = tid & 31;
    const int grp  = lane >> 2;
    const int tig  = lane & 3;
    const int m0   = wid * 16;

    // ---- load + pack Q (scaled), hi/lo split, 64-bit stores ----
#pragma unroll
    for (int it = 0; it < 8; it++) {
        int idx = tid + it * 256;
        int r = idx >> 4, c4 = idx & 15;
        float4 v = *(const float4*)(Qg + (size_t)r * CC + c4 * 4);
        v.x *= 0.125f; v.y *= 0.125f; v.z *= 0.125f; v.w *= 0.125f;
        uint32_t h0, l0, h1, l1;
        split2(v.x, v.y, h0, l0);
        split2(v.z, v.w, h1, l1);
        *(uint2*)(Qhi + r * QKST + 2 * c4) = make_uint2(h0, h1);
        *(uint2*)(Qlo + r * QKST + 2 * c4) = make_uint2(l0, l1);
    }
    __syncthreads();

    // ---- hoist Q A-fragments (k-permuted 64-bit: hw slots (tig,tig+4) <- words (2tig,2tig+1)) ----
    uint32_t qa_h[4][4], qa_l[4][4];
#pragma unroll
    for (int c = 0; c < 4; c++) {
        const int w0 = 8 * c + 2 * tig;
        uint2 q0h = *(const uint2*)(Qhi + (m0 + grp) * QKST + w0);
        uint2 q1h = *(const uint2*)(Qhi + (m0 + grp + 8) * QKST + w0);
        uint2 q0l = *(const uint2*)(Qlo + (m0 + grp) * QKST + w0);
        uint2 q1l = *(const uint2*)(Qlo + (m0 + grp + 8) * QKST + w0);
        qa_h[c][0] = q0h.x; qa_h[c][1] = q1h.x; qa_h[c][2] = q0h.y; qa_h[c][3] = q1h.y;
        qa_l[c][0] = q0l.x; qa_l[c][1] = q1l.x; qa_l[c][2] = q0l.y; qa_l[c][3] = q1l.y;
    }

    float oacc[8][4];
#pragma unroll
    for (int i = 0; i < 8; i++)
#pragma unroll
        for (int j = 0; j < 4; j++) oacc[i][j] = 0.f;
    float m_r0 = -INFINITY, m_r1 = -INFINITY, l_r0 = 0.f, l_r1 = 0.f;

    // ---- prologue loads for tile 0 ----
    float4 kreg[4], va[2], vb[2];
#pragma unroll
    for (int it = 0; it < 4; it++) {
        int idx = tid + it * 256;
        int r = idx >> 4, c4 = idx & 15;
        kreg[it] = *(const float4*)(Kg + (size_t)r * (NG * HD) + c4 * 4);
    }
#pragma unroll
    for (int it = 0; it < 2; it++) {
        int idx = tid + it * 256;
        int rp = idx >> 4, c4 = idx & 15;
        va[it] = *(const float4*)(Vg + (size_t)(2 * rp) * (NG * HD) + c4 * 4);
        vb[it] = *(const float4*)(Vg + (size_t)(2 * rp + 1) * (NG * HD) + c4 * 4);
    }

    for (int kv = 0; kv < TT; kv += 64) {
        __syncthreads();

        // ---- pack K (64-bit stores) ----
#pragma unroll
        for (int it = 0; it < 4; it++) {
            int idx = tid + it * 256;
            int r = idx >> 4, c4 = idx & 15;
            uint32_t h0, l0, h1, l1;
            split2(kreg[it].x, kreg[it].y, h0, l0);
            split2(kreg[it].z, kreg[it].w, h1, l1);
            *(uint2*)(Khi + r * QKST + 2 * c4) = make_uint2(h0, h1);
            *(uint2*)(Klo + r * QKST + 2 * c4) = make_uint2(l0, l1);
        }
        // ---- pack V transposed (scalar, layout fixed by P's k-mapping) ----
#pragma unroll
        for (int it = 0; it < 2; it++) {
            int idx = tid + it * 256;
            int rp = idx >> 4, c4 = idx & 15;
            float av[4] = {va[it].x, va[it].y, va[it].z, va[it].w};
            float bv[4] = {vb[it].x, vb[it].y, vb[it].z, vb[it].w};
#pragma unroll
            for (int j = 0; j < 4; j++) {
                uint32_t hw, lw;
                split2(av[j], bv[j], hw, lw);
                Vhi[(4 * c4 + j) * VST + rp] = hw;
                Vlo[(4 * c4 + j) * VST + rp] = lw;
            }
        }

        // ---- prefetch next tile's K/V ----
        if (kv + 64 < TT) {
            const float* Kn = Kg + (size_t)(kv + 64) * (NG * HD);
            const float* Vn = Vg + (size_t)(kv + 64) * (NG * HD);
#pragma unroll
            for (int it = 0; it < 4; it++) {
                int idx = tid + it * 256;
                int r = idx >> 4, c4 = idx & 15;
                kreg[it] = *(const float4*)(Kn + (size_t)r * (NG * HD) + c4 * 4);
            }
#pragma unroll
            for (int it = 0; it < 2; it++) {
                int idx = tid + it * 256;
                int rp = idx >> 4, c4 = idx & 15;
                va[it] = *(const float4*)(Vn + (size_t)(2 * rp) * (NG * HD) + c4 * 4);
                vb[it] = *(const float4*)(Vn + (size_t)(2 * rp + 1) * (NG * HD) + c4 * 4);
            }
        }
        __syncthreads();

        // ---- S = Q @ K^T (64-bit permuted B-frag loads) ----
        float sacc[8][4];
#pragma unroll
        for (int i = 0; i < 8; i++)
#pragma unroll
            for (int j = 0; j < 4; j++) sacc[i][j] = 0.f;
#pragma unroll
        for (int c = 0; c < 4; c++) {
#pragma unroll
            for (int gg = 0; gg < 8; gg++) {
                const int rowk = (8 * gg + grp) * QKST + 8 * c + 2 * tig;
                uint2 kh = *(const uint2*)(Khi + rowk);
                uint2 kl = *(const uint2*)(Klo + rowk);
                mma_bf16(sacc[gg], qa_h[c][0], qa_h[c][1], qa_h[c][2], qa_h[c][3], kh.x, kh.y);
                mma_bf16(sacc[gg], qa_h[c][0], qa_h[c][1], qa_h[c][2], qa_h[c][3], kl.x, kl.y);
                mma_bf16(sacc[gg], qa_l[c][0], qa_l[c][1], qa_l[c][2], qa_l[c][3], kh.x, kh.y);
            }
        }

        // ---- online softmax ----
        float rm0 = -INFINITY, rm1 = -INFINITY;
#pragma unroll
        for (int gg = 0; gg < 8; gg++) {
            rm0 = fmaxf(rm0, fmaxf(sacc[gg][0], sacc[gg][1]));
            rm1 = fmaxf(rm1, fmaxf(sacc[gg][2], sacc[gg][3]));
        }
        rm0 = fmaxf(rm0, __shfl_xor_sync(0xffffffffu, rm0, 1));
        rm0 = fmaxf(rm0, __shfl_xor_sync(0xffffffffu, rm0, 2));
        rm1 = fmaxf(rm1, __shfl_xor_sync(0xffffffffu, rm1, 1));
        rm1 = fmaxf(rm1, __shfl_xor_sync(0xffffffffu, rm1, 2));

        float nm0 = fmaxf(m_r0, rm0), nm1 = fmaxf(m_r1, rm1);
        float sc0 = __expf(m_r0 - nm0), sc1 = __expf(m_r1 - nm1);
        m_r0 = nm0; m_r1 = nm1;

        float rs0 = 0.f, rs1 = 0.f;
#pragma unroll
        for (int gg = 0; gg < 8; gg++) {
            sacc[gg][0] = __expf(sacc[gg][0] - nm0);
            sacc[gg][1] = __expf(sacc[gg][1] - nm0);
            sacc[gg][2] = __expf(sacc[gg][2] - nm1);
            sacc[gg][3] = __expf(sacc[gg][3] - nm1);
            rs0 += sacc[gg][0] + sacc[gg][1];
            rs1 += sacc[gg][2] + sacc[gg][3];
        }
        rs0 += __shfl_xor_sync(0xffffffffu, rs0, 1);
        rs0 += __shfl_xor_sync(0xffffffffu, rs0, 2);
        rs1 += __shfl_xor_sync(0xffffffffu, rs1, 1);
        rs1 += __shfl_xor_sync(0xffffffffu, rs1, 2);
        l_r0 = l_r0 * sc0 + rs0;
        l_r1 = l_r1 * sc1 + rs1;
#pragma unroll
        for (int i = 0; i < 8; i++) {
            oacc[i][0] *= sc0; oacc[i][1] *= sc0;
            oacc[i][2] *= sc1; oacc[i][3] *= sc1;
        }

        // ---- pack P hi/lo ----
        uint32_t phi[8][2], plo[8][2];
#pragma unroll
        for (int gg = 0; gg < 8; gg++) {
            split2(sacc[gg][0], sacc[gg][1], phi[gg][0], plo[gg][0]);
            split2(sacc[gg][2], sacc[gg][3], phi[gg][1], plo[gg][1]);
        }

        // ---- O += P @ V (scalar V loads, layout pinned by P) ----
#pragma unroll
        for (int c = 0; c < 4; c++) {
            uint32_t ah0 = phi[2 * c][0],     ah1 = phi[2 * c][1];
            uint32_t ah2 = phi[2 * c + 1][0], ah3 = phi[2 * c + 1][1];
            uint32_t al0 = plo[2 * c][0],     al1 = plo[2 * c][1];
            uint32_t al2 = plo[2 * c + 1][0], al3 = plo[2 * c + 1][1];
#pragma unroll
            for (int hh = 0; hh < 8; hh++) {
                const int rowv = (8 * hh + grp) * VST + 8 * c + tig;
                uint32_t bh0 = Vhi[rowv], bh1 = Vhi[rowv + 4];
                uint32_t bl0 = Vlo[rowv], bl1 = Vlo[rowv + 4];
                mma_bf16(oacc[hh], ah0, ah1, ah2, ah3, bh0, bh1);
                mma_bf16(oacc[hh], ah0, ah1, ah2, ah3, bl0, bl1);
                mma_bf16(oacc[hh], al0, al1, al2, al3, bh0, bh1);
            }
        }
    }

    // ---- normalize + tf32-round + store (out-proj consumes this directly) ----
    const float inv0 = 1.0f / l_r0, inv1 = 1.0f / l_r1;
    float* Og = O + ((size_t)b * TT + q0) * CC + h * HD;
    const int r0 = m0 + grp, r1 = m0 + grp + 8;
#pragma unroll
    for (int hh = 0; hh < 8; hh++) {
        const int col = 8 * hh + 2 * tig;
        float2 v0 = make_float2(__uint_as_float(f2tf32(oacc[hh][0] * inv0)),
                                __uint_as_float(f2tf32(oacc[hh][1] * inv0)));
        float2 v1 = make_float2(__uint_as_float(f2tf32(oacc[hh][2] * inv1)),
                                __uint_as_float(f2tf32(oacc[hh][3] * inv1)));
        *(float2*)(Og + (size_t)r0 * CC + col) = v0;
        *(float2*)(Og + (size_t)r1 * CC + col) = v1;
    }
}

// ---------------- launch ----------------
extern "C" void kernel_launch(void* const* d_in, const int* in_sizes, int n_in,
                              void* d_out, int out_size)
{
    const float* q  = (const float*)d_in[0];
    const float* k  = (const float*)d_in[1];
    const float* v  = (const float*)d_in[2];
    const float* Wq = (const float*)d_in[3];
    const float* Wk = (const float*)d_in[4];
    const float* Wv = (const float*)d_in[5];
    const float* Wp = (const float*)d_in[6];
    const float* bp = (const float*)d_in[7];
    float* out = (float*)d_out;

    float *pQP, *pKP, *pVP, *pO, *pqc, *pkc, *pvc, *pwq, *pwk, *pwv, *pwp;
    cudaGetSymbolAddress((void**)&pQP, g_QP);
    cudaGetSymbolAddress((void**)&pKP, g_KP);
    cudaGetSymbolAddress((void**)&pVP, g_VP);
    cudaGetSymbolAddress((void**)&pO,  g_O);
    cudaGetSymbolAddress((void**)&pqc, g_qc);
    cudaGetSymbolAddress((void**)&pkc, g_kc);
    cudaGetSymbolAddress((void**)&pvc, g_vc);
    cudaGetSymbolAddress((void**)&pwq, g_wq);
    cudaGetSymbolAddress((void**)&pwk, g_wk);
    cudaGetSymbolAddress((void**)&pwv, g_wv);
    cudaGetSymbolAddress((void**)&pwp, g_wp);

    cudaFuncSetAttribute(gemm_tc, cudaFuncAttributeMaxDynamicSharedMemorySize, GEMM_SMEM_BYTES);
    cudaFuncSetAttribute(gemm_kv, cudaFuncAttributeMaxDynamicSharedMemorySize, GEMM_SMEM_BYTES);
    cudaFuncSetAttribute(attn_mma, cudaFuncAttributeMaxDynamicSharedMemorySize, ATTN_SMEM_BYTES);

    const int M = BB * TT;  // 4096
    const int NBIG = M * CC / 4;
    const int NWQ  = CC * CC / 4;
    const int NWK  = NG * HD * CC / 4;

    conv_tf32<<<(NBIG + 255) / 256, 256>>>(q, pqc, NBIG);
    conv_tf32<<<(NBIG + 255) / 256, 256>>>(k, pkc, NBIG);
    conv_tf32<<<(NBIG + 255) / 256, 256>>>(v, pvc, NBIG);
    conv_tf32<<<(NWQ + 255) / 256, 256>>>(Wq, pwq, NWQ);
    conv_tf32<<<(NWK + 255) / 256, 256>>>(Wk, pwk, NWK);
    conv_tf32<<<(NWK + 255) / 256, 256>>>(Wv, pwv, NWK);
    conv_tf32<<<(NWQ + 255) / 256, 256>>>(Wp, pwp, NWQ);

    gemm_tc<<<dim3(CC / 128, M / 128), 256, GEMM_SMEM_BYTES>>>(pqc, pwq, nullptr, pQP, CC, CC);
    gemm_kv<<<dim3(8, M / 128), 256, GEMM_SMEM_BYTES>>>(pkc, pvc, pwk, pwv, pKP, pVP);

    attn_mma<<<dim3(TT / 128, BB * NH), 256, ATTN_SMEM_BYTES>>>(pQP, pKP, pVP, pO);

    gemm_tc<<<dim3(CC / 128, M / 128), 256, GEMM_SMEM_BYTES>>>(pO, pwp, bp, out, CC, CC);
}

// round 7
// speedup vs baseline: 3.6281x; 1.1079x over previous
#include <cuda_runtime.h>
#include <cuda_bf16.h>
#include <cstdint>
#include <math.h>

#define BB 2
#define TT 2048
#define CC 2048
#define NH 32
#define NG 8
#define HD 64

// ---------------- scratch (no allocations allowed) ----------------
__device__ float g_QP[BB * TT * CC];
__device__ float g_VP[BB * TT * NG * HD];
__device__ float g_O [BB * TT * CC];
__device__ float g_qc[BB * TT * CC];
__device__ float g_kc[BB * TT * CC];
__device__ float g_vc[BB * TT * CC];
__device__ float g_wq[CC * CC];
__device__ float g_wk[NG * HD * CC];
__device__ float g_wv[NG * HD * CC];
__device__ float g_wp[CC * CC];
// pre-packed bf16 hi/lo K (word = hd pair) and transposed V (word = kv pair)
__device__ uint32_t g_Khi[BB * NG * TT * 32];
__device__ uint32_t g_Klo[BB * NG * TT * 32];
__device__ uint32_t g_Vhi[BB * NG * 64 * (TT / 2)];
__device__ uint32_t g_Vlo[BB * NG * 64 * (TT / 2)];

// ---------------- helpers ----------------
__device__ __forceinline__ uint32_t f2tf32(float x) {
    uint32_t r;
    asm("cvt.rna.tf32.f32 %0, %1;" : "=r"(r) : "f"(x));
    return r;
}
__device__ __forceinline__ void mma_tf32(float& d0, float& d1, float& d2, float& d3,
                                         uint32_t a0, uint32_t a1, uint32_t a2, uint32_t a3,
                                         uint32_t b0, uint32_t b1)
{
    asm volatile(
        "mma.sync.aligned.m16n8k8.row.col.f32.tf32.tf32.f32 "
        "{%0,%1,%2,%3}, {%4,%5,%6,%7}, {%8,%9}, {%0,%1,%2,%3};"
        : "+f"(d0), "+f"(d1), "+f"(d2), "+f"(d3)
        : "r"(a0), "r"(a1), "r"(a2), "r"(a3), "r"(b0), "r"(b1));
}
__device__ __forceinline__ void mma_bf16(float* d,
                                         uint32_t a0, uint32_t a1, uint32_t a2, uint32_t a3,
                                         uint32_t b0, uint32_t b1)
{
    asm volatile(
        "mma.sync.aligned.m16n8k16.row.col.f32.bf16.bf16.f32 "
        "{%0,%1,%2,%3}, {%4,%5,%6,%7}, {%8,%9}, {%0,%1,%2,%3};"
        : "+f"(d[0]), "+f"(d[1]), "+f"(d[2]), "+f"(d[3])
        : "r"(a0), "r"(a1), "r"(a2), "r"(a3), "r"(b0), "r"(b1));
}
__device__ __forceinline__ uint32_t packbf2(float a, float b) {
    __nv_bfloat162 t = __floats2bfloat162_rn(a, b);
    return *(uint32_t*)&t;
}
__device__ __forceinline__ void split2(float a, float b, uint32_t& hi, uint32_t& lo) {
    __nv_bfloat16 ah = __float2bfloat16_rn(a);
    __nv_bfloat16 bh = __float2bfloat16_rn(b);
    float ar = a - __bfloat162float(ah);
    float br = b - __bfloat162float(bh);
    __nv_bfloat162 h; h.x = ah; h.y = bh;
    hi = *(uint32_t*)&h;
    lo = packbf2(ar, br);
}
__device__ __forceinline__ uint32_t smem_u32(const void* p) {
    uint32_t a;
    asm("{ .reg .u64 t; cvta.to.shared.u64 t, %1; cvt.u32.u64 %0, t; }" : "=r"(a) : "l"(p));
    return a;
}
__device__ __forceinline__ void cp16(uint32_t dst, const void* src) {
    asm volatile("cp.async.ca.shared.global [%0], [%1], 16;" :: "r"(dst), "l"(src));
}
__device__ __forceinline__ void cp_commit() { asm volatile("cp.async.commit_group;" ::: "memory"); }
template<int N> __device__ __forceinline__ void cp_wait() {
    asm volatile("cp.async.wait_group %0;" :: "n"(N) : "memory");
}

// ---------------- tf32 conversion (elementwise) ----------------
__global__ void __launch_bounds__(256) conv_tf32(const float* __restrict__ s,
                                                 float* __restrict__ d, int n4)
{
    int i = blockIdx.x * 256 + threadIdx.x;
    if (i >= n4) return;
    float4 v = ((const float4*)s)[i];
    v.x = __uint_as_float(f2tf32(v.x));
    v.y = __uint_as_float(f2tf32(v.y));
    v.z = __uint_as_float(f2tf32(v.z));
    v.w = __uint_as_float(f2tf32(v.w));
    ((float4*)d)[i] = v;
}

// ---------------- V pack+transpose: VP fp32 (b,t,g,d) -> Vt hi/lo (bg,hd,t/2 words) ----------------
__global__ void __launch_bounds__(256) pack_v(const float* __restrict__ VP,
                                              uint32_t* __restrict__ Vhi,
                                              uint32_t* __restrict__ Vlo)
{
    __shared__ float tile[64][65];
    const int bg = blockIdx.y;
    const int b  = bg >> 3, g = bg & 7;
    const int t0 = blockIdx.x * 64;
    const int tid = threadIdx.x;

#pragma unroll
    for (int it = 0; it < 4; it++) {
        int idx = tid + it * 256;           // float4 id
        int tl = idx >> 4, c4 = idx & 15;
        float4 v = *(const float4*)(VP + ((size_t)b * TT + t0 + tl) * (NG * HD) + g * 64 + c4 * 4);
        tile[tl][c4 * 4 + 0] = v.x; tile[tl][c4 * 4 + 1] = v.y;
        tile[tl][c4 * 4 + 2] = v.z; tile[tl][c4 * 4 + 3] = v.w;
    }
    __syncthreads();
#pragma unroll
    for (int it = 0; it < 8; it++) {
        int idx = tid + it * 256;           // word id
        int hd = idx >> 5, t2 = idx & 31;
        uint32_t hi, lo;
        split2(tile[2 * t2][hd], tile[2 * t2 + 1][hd], hi, lo);
        size_t o = ((size_t)bg * 64 + hd) * (TT / 2) + (t0 >> 1) + t2;
        Vhi[o] = hi;
        Vlo[o] = lo;
    }
}

// ============== cp.async tf32 GEMM, 64-bit permuted fragment loads ==============
#define GST 24
#define STGF (2 * 128 * GST)
#define GEMM_SMEM_BYTES (4 * STGF * 4)

__device__ __forceinline__ void gemm_body(
    const float* __restrict__ A, const float* __restrict__ Bm,
    const float* __restrict__ bias, float* __restrict__ Cm,
    int N, int K, int bm, int bn,
    uint32_t* __restrict__ Khi, uint32_t* __restrict__ Klo)   // non-null -> packed-K epilogue
{
    extern __shared__ float smem[];
    const uint32_t smb = smem_u32(smem);

    const int tid  = threadIdx.x;
    const int wid  = tid >> 5;
    const int lane = tid & 31;
    const int grp  = lane >> 2;
    const int tig  = lane & 3;
    const int warp_m = wid >> 2;
    const int warp_n = wid & 3;

    const int srow = tid >> 2;
    const int scg  = (tid & 3) * 4;
    const float* Ag = A  + (size_t)(bm + srow) * K + scg;
    const float* Bg = Bm + (size_t)(bn + srow) * K + scg;
    const uint32_t a_dst = smb + (uint32_t)(srow * GST + scg) * 4;
    const uint32_t HALF  = (uint32_t)(64 * GST) * 4;
    const uint32_t BOFF  = (uint32_t)(128 * GST) * 4;

    float acc[4][4][4];
#pragma unroll
    for (int i = 0; i < 4; i++)
#pragma unroll
        for (int j = 0; j < 4; j++)
#pragma unroll
            for (int r = 0; r < 4; r++) acc[i][j][r] = 0.f;

    const int NSTAGE = K / 16;

#define GEMM_ISSUE(sl, it) do {                                      \
        const int _k0 = (it) * 16;                                   \
        const uint32_t _ab = a_dst + (uint32_t)(sl) * (STGF * 4);    \
        cp16(_ab,               Ag + _k0);                           \
        cp16(_ab + HALF,        Ag + 64 * (size_t)K + _k0);          \
        cp16(_ab + BOFF,        Bg + _k0);                           \
        cp16(_ab + BOFF + HALF, Bg + 64 * (size_t)K + _k0);          \
    } while (0)

    GEMM_ISSUE(0, 0); cp_commit();
    GEMM_ISSUE(1, 1); cp_commit();
    GEMM_ISSUE(2, 2); cp_commit();

    for (int it = 0; it < NSTAGE; it++) {
        cp_wait<2>();
        __syncthreads();
        if (it + 3 < NSTAGE) { GEMM_ISSUE((it + 3) & 3, it + 3); }
        cp_commit();

        const float* Asb = smem + (it & 3) * STGF;
        const float* Bsb = Asb + 128 * GST;
#pragma unroll
        for (int kk = 0; kk < 16; kk += 8) {
            uint2 bfr[4];
#pragma unroll
            for (int na = 0; na < 4; na++)
                bfr[na] = *(const uint2*)(Bsb + (warp_n * 32 + na * 8 + grp) * GST + kk + 2 * tig);
#pragma unroll
            for (int ma = 0; ma < 4; ma++) {
                uint2 av0 = *(const uint2*)(Asb + (warp_m * 64 + ma * 16 + grp) * GST + kk + 2 * tig);
                uint2 av1 = *(const uint2*)(Asb + (warp_m * 64 + ma * 16 + 8 + grp) * GST + kk + 2 * tig);
#pragma unroll
                for (int na = 0; na < 4; na++) {
                    mma_tf32(acc[ma][na][0], acc[ma][na][1], acc[ma][na][2], acc[ma][na][3],
                             av0.x, av1.x, av0.y, av1.y, bfr[na].x, bfr[na].y);
                }
            }
        }
    }
#undef GEMM_ISSUE

    if (Khi) {
        // packed-K epilogue: word = adjacent hd pair (col, col+1); row -> (b, t)
#pragma unroll
        for (int na = 0; na < 4; na++) {
            const int col = bn + warp_n * 32 + na * 8 + 2 * tig;  // 0..511
            const int g   = col >> 6;
            const int wrd = (col & 63) >> 1;
#pragma unroll
            for (int ma = 0; ma < 4; ma++) {
                const int row = bm + warp_m * 64 + ma * 16 + grp;
                const int b = row >> 11, t = row & (TT - 1);
                size_t o = ((size_t)(b * NG + g) * TT + t) * 32 + wrd;
                uint32_t hi, lo;
                split2(acc[ma][na][0], acc[ma][na][1], hi, lo);
                Khi[o] = hi; Klo[o] = lo;
                split2(acc[ma][na][2], acc[ma][na][3], hi, lo);
                Khi[o + 8 * 32] = hi; Klo[o + 8 * 32] = lo;    // t+8
            }
        }
    } else {
#pragma unroll
        for (int na = 0; na < 4; na++) {
            const int col = bn + warp_n * 32 + na * 8 + 2 * tig;
            float b0 = 0.f, b1 = 0.f;
            if (bias) { b0 = bias[col]; b1 = bias[col + 1]; }
#pragma unroll
            for (int ma = 0; ma < 4; ma++) {
                const int row = bm + warp_m * 64 + ma * 16 + grp;
                float2 v0 = make_float2(acc[ma][na][0] + b0, acc[ma][na][1] + b1);
                float2 v1 = make_float2(acc[ma][na][2] + b0, acc[ma][na][3] + b1);
                *(float2*)(Cm + (size_t)row * N + col) = v0;
                *(float2*)(Cm + (size_t)(row + 8) * N + col) = v1;
            }
        }
    }
}

__global__ void __launch_bounds__(256, 2) gemm_tc(
    const float* __restrict__ A, const float* __restrict__ Bm,
    const float* __restrict__ bias, float* __restrict__ Cm, int N, int K)
{
    gemm_body(A, Bm, bias, Cm, N, K, blockIdx.y * 128, blockIdx.x * 128, nullptr, nullptr);
}

// fused K+V projections; K branch emits packed bf16 hi/lo directly
__global__ void __launch_bounds__(256, 2) gemm_kv(
    const float* __restrict__ kc, const float* __restrict__ vc,
    const float* __restrict__ wk, const float* __restrict__ wv,
    uint32_t* __restrict__ Khi, uint32_t* __restrict__ Klo,
    float* __restrict__ VP)
{
    const bool isV = blockIdx.x >= 4;
    if (isV)
        gemm_body(vc, wv, nullptr, VP, NG * HD, CC, blockIdx.y * 128, (blockIdx.x & 3) * 128,
                  nullptr, nullptr);
    else
        gemm_body(kc, wk, nullptr, nullptr, NG * HD, CC, blockIdx.y * 128, (blockIdx.x & 3) * 128,
                  Khi, Klo);
}

// ============== flash attention: pre-packed K/V, cp.async 2-stage ring, register Q ==============
#define QKST 40
#define VST  36
#define STW  9728     // words per stage: 2*64*40 (K hi/lo) + 2*64*36 (V hi/lo)
#define ATTN_SMEM_BYTES (2 * STW * 4)   // 77824

__global__ void __launch_bounds__(256, 1) attn_mma(
    const float* __restrict__ QP,
    const uint32_t* __restrict__ Kghi, const uint32_t* __restrict__ Kglo,
    const uint32_t* __restrict__ Vghi, const uint32_t* __restrict__ Vglo,
    float* __restrict__ O)
{
    extern __shared__ uint32_t sm[];
    const uint32_t smb = smem_u32(sm);

    const int bh = blockIdx.y;
    const int b  = bh >> 5;
    const int h  = bh & 31;
    const int g  = h & 7;
    const int bg = b * NG + g;
    const int q0 = blockIdx.x * 128;

    const float* Qg = QP + ((size_t)b * TT + q0) * CC + h * HD;
    const uint32_t* Kh = Kghi + (size_t)bg * TT * 32;
    const uint32_t* Kl = Kglo + (size_t)bg * TT * 32;
    const uint32_t* Vh = Vghi + (size_t)bg * 64 * (TT / 2);
    const uint32_t* Vl = Vglo + (size_t)bg * 64 * (TT / 2);

    const int tid  = threadIdx.x;
    const int wid  = tid >> 5;
    const int lane = tid & 31;
    const int grp  = lane >> 2;
    const int tig  = lane & 3;
    const int m0   = wid * 16;

    // issue one 64-key tile of K+V into stage s (8 cp16 per thread)
#define ATTN_ISSUE(s, kv) do {                                                            \
        _Pragma("unroll")                                                                 \
        for (int _it = 0; _it < 4; _it++) {                                               \
            int _ch = tid + _it * 256;                                                    \
            int _arr = _ch >> 9, _rem = _ch & 511;                                        \
            int _r = _rem >> 3, _c = _rem & 7;                                            \
            const uint32_t* _src = (_arr ? Kl : Kh) + ((size_t)((kv) + _r) * 32 + _c * 4);\
            cp16(smb + (uint32_t)((s) * STW + _arr * 2560 + _r * QKST + _c * 4) * 4, _src);\
        }                                                                                 \
        _Pragma("unroll")                                                                 \
        for (int _it = 0; _it < 4; _it++) {                                               \
            int _ch = tid + _it * 256;                                                    \
            int _arr = _ch >> 9, _rem = _ch & 511;                                        \
            int _hd = _rem >> 3, _c = _rem & 7;                                           \
            const uint32_t* _src = (_arr ? Vl : Vh) + ((size_t)_hd * (TT / 2) + ((kv) >> 1) + _c * 4);\
            cp16(smb + (uint32_t)((s) * STW + 5120 + _arr * 2304 + _hd * VST + _c * 4) * 4, _src);\
        }                                                                                 \
    } while (0)

    ATTN_ISSUE(0, 0);  cp_commit();
    ATTN_ISSUE(1, 64); cp_commit();

    // ---- Q fragments straight from gmem (no smem): word w=8c+2tig covers hd (16c+4tig, +1) ----
    uint32_t qa_h[4][4], qa_l[4][4];
#pragma unroll
    for (int c = 0; c < 4; c++) {
#pragma unroll
        for (int rr = 0; rr < 2; rr++) {
            const int row = m0 + grp + rr * 8;
            float4 v = *(const float4*)(Qg + (size_t)row * CC + 16 * c + 4 * tig);
            v.x *= 0.125f; v.y *= 0.125f; v.z *= 0.125f; v.w *= 0.125f;
            uint32_t h0, l0, h1, l1;
            split2(v.x, v.y, h0, l0);
            split2(v.z, v.w, h1, l1);
            qa_h[c][rr] = h0; qa_h[c][rr + 2] = h1;
            qa_l[c][rr] = l0; qa_l[c][rr + 2] = l1;
        }
    }

    float oacc[8][4];
#pragma unroll
    for (int i = 0; i < 8; i++)
#pragma unroll
        for (int j = 0; j < 4; j++) oacc[i][j] = 0.f;
    float m_r0 = -INFINITY, m_r1 = -INFINITY, l_r0 = 0.f, l_r1 = 0.f;

    for (int tile = 0; tile < TT / 64; tile++) {
        cp_wait<1>();
        __syncthreads();
        const int s = tile & 1;
        const uint32_t* Khi = sm + s * STW;
        const uint32_t* Klo = Khi + 2560;
        const uint32_t* Vhi = Khi + 5120;
        const uint32_t* Vlo = Khi + 7424;

        // ---- S = Q @ K^T ----
        float sacc[8][4];
#pragma unroll
        for (int i = 0; i < 8; i++)
#pragma unroll
            for (int j = 0; j < 4; j++) sacc[i][j] = 0.f;
#pragma unroll
        for (int c = 0; c < 4; c++) {
#pragma unroll
            for (int gg = 0; gg < 8; gg++) {
                const int rowk = (8 * gg + grp) * QKST + 8 * c + 2 * tig;
                uint2 kh = *(const uint2*)(Khi + rowk);
                uint2 kl = *(const uint2*)(Klo + rowk);
                mma_bf16(sacc[gg], qa_h[c][0], qa_h[c][1], qa_h[c][2], qa_h[c][3], kh.x, kh.y);
                mma_bf16(sacc[gg], qa_h[c][0], qa_h[c][1], qa_h[c][2], qa_h[c][3], kl.x, kl.y);
                mma_bf16(sacc[gg], qa_l[c][0], qa_l[c][1], qa_l[c][2], qa_l[c][3], kh.x, kh.y);
            }
        }

        // ---- online softmax ----
        float rm0 = -INFINITY, rm1 = -INFINITY;
#pragma unroll
        for (int gg = 0; gg < 8; gg++) {
            rm0 = fmaxf(rm0, fmaxf(sacc[gg][0], sacc[gg][1]));
            rm1 = fmaxf(rm1, fmaxf(sacc[gg][2], sacc[gg][3]));
        }
        rm0 = fmaxf(rm0, __shfl_xor_sync(0xffffffffu, rm0, 1));
        rm0 = fmaxf(rm0, __shfl_xor_sync(0xffffffffu, rm0, 2));
        rm1 = fmaxf(rm1, __shfl_xor_sync(0xffffffffu, rm1, 1));
        rm1 = fmaxf(rm1, __shfl_xor_sync(0xffffffffu, rm1, 2));

        float nm0 = fmaxf(m_r0, rm0), nm1 = fmaxf(m_r1, rm1);
        float sc0 = __expf(m_r0 - nm0), sc1 = __expf(m_r1 - nm1);
        m_r0 = nm0; m_r1 = nm1;

        float rs0 = 0.f, rs1 = 0.f;
#pragma unroll
        for (int gg = 0; gg < 8; gg++) {
            sacc[gg][0] = __expf(sacc[gg][0] - nm0);
            sacc[gg][1] = __expf(sacc[gg][1] - nm0);
            sacc[gg][2] = __expf(sacc[gg][2] - nm1);
            sacc[gg][3] = __expf(sacc[gg][3] - nm1);
            rs0 += sacc[gg][0] + sacc[gg][1];
            rs1 += sacc[gg][2] + sacc[gg][3];
        }
        rs0 += __shfl_xor_sync(0xffffffffu, rs0, 1);
        rs0 += __shfl_xor_sync(0xffffffffu, rs0, 2);
        rs1 += __shfl_xor_sync(0xffffffffu, rs1, 1);
        rs1 += __shfl_xor_sync(0xffffffffu, rs1, 2);
        l_r0 = l_r0 * sc0 + rs0;
        l_r1 = l_r1 * sc1 + rs1;
#pragma unroll
        for (int i = 0; i < 8; i++) {
            oacc[i][0] *= sc0; oacc[i][1] *= sc0;
            oacc[i][2] *= sc1; oacc[i][3] *= sc1;
        }

        // ---- pack P hi/lo ----
        uint32_t phi[8][2], plo[8][2];
#pragma unroll
        for (int gg = 0; gg < 8; gg++) {
            split2(sacc[gg][0], sacc[gg][1], phi[gg][0], plo[gg][0]);
            split2(sacc[gg][2], sacc[gg][3], phi[gg][1], plo[gg][1]);
        }

        // ---- O += P @ V ----
#pragma unroll
        for (int c = 0; c < 4; c++) {
            uint32_t ah0 = phi[2 * c][0],     ah1 = phi[2 * c][1];
            uint32_t ah2 = phi[2 * c + 1][0], ah3 = phi[2 * c + 1][1];
            uint32_t al0 = plo[2 * c][0],     al1 = plo[2 * c][1];
            uint32_t al2 = plo[2 * c + 1][0], al3 = plo[2 * c + 1][1];
#pragma unroll
            for (int hh = 0; hh < 8; hh++) {
                const int rowv = (8 * hh + grp) * VST + 8 * c + tig;
                uint32_t bh0 = Vhi[rowv], bh1 = Vhi[rowv + 4];
                uint32_t bl0 = Vlo[rowv], bl1 = Vlo[rowv + 4];
                mma_bf16(oacc[hh], ah0, ah1, ah2, ah3, bh0, bh1);
                mma_bf16(oacc[hh], ah0, ah1, ah2, ah3, bl0, bl1);
                mma_bf16(oacc[hh], al0, al1, al2, al3, bh0, bh1);
            }
        }

        __syncthreads();   // all warps done with stage s before refilling it
        if (tile + 2 < TT / 64) { ATTN_ISSUE(s, (tile + 2) * 64); }
        cp_commit();
    }
#undef ATTN_ISSUE

    // ---- normalize + tf32-round + store ----
    const float inv0 = 1.0f / l_r0, inv1 = 1.0f / l_r1;
    float* Og = O + ((size_t)b * TT + q0) * CC + h * HD;
    const int r0 = m0 + grp, r1 = m0 + grp + 8;
#pragma unroll
    for (int hh = 0; hh < 8; hh++) {
        const int col = 8 * hh + 2 * tig;
        float2 v0 = make_float2(__uint_as_float(f2tf32(oacc[hh][0] * inv0)),
                                __uint_as_float(f2tf32(oacc[hh][1] * inv0)));
        float2 v1 = make_float2(__uint_as_float(f2tf32(oacc[hh][2] * inv1)),
                                __uint_as_float(f2tf32(oacc[hh][3] * inv1)));
        *(float2*)(Og + (size_t)r0 * CC + col) = v0;
        *(float2*)(Og + (size_t)r1 * CC + col) = v1;
    }
}

// ---------------- launch ----------------
extern "C" void kernel_launch(void* const* d_in, const int* in_sizes, int n_in,
                              void* d_out, int out_size)
{
    const float* q  = (const float*)d_in[0];
    const float* k  = (const float*)d_in[1];
    const float* v  = (const float*)d_in[2];
    const float* Wq = (const float*)d_in[3];
    const float* Wk = (const float*)d_in[4];
    const float* Wv = (const float*)d_in[5];
    const float* Wp = (const float*)d_in[6];
    const float* bp = (const float*)d_in[7];
    float* out = (float*)d_out;

    float *pQP, *pVP, *pO, *pqc, *pkc, *pvc, *pwq, *pwk, *pwv, *pwp;
    uint32_t *pKhi, *pKlo, *pVhi, *pVlo;
    cudaGetSymbolAddress((void**)&pQP, g_QP);
    cudaGetSymbolAddress((void**)&pVP, g_VP);
    cudaGetSymbolAddress((void**)&pO,  g_O);
    cudaGetSymbolAddress((void**)&pqc, g_qc);
    cudaGetSymbolAddress((void**)&pkc, g_kc);
    cudaGetSymbolAddress((void**)&pvc, g_vc);
    cudaGetSymbolAddress((void**)&pwq, g_wq);
    cudaGetSymbolAddress((void**)&pwk, g_wk);
    cudaGetSymbolAddress((void**)&pwv, g_wv);
    cudaGetSymbolAddress((void**)&pwp, g_wp);
    cudaGetSymbolAddress((void**)&pKhi, g_Khi);
    cudaGetSymbolAddress((void**)&pKlo, g_Klo);
    cudaGetSymbolAddress((void**)&pVhi, g_Vhi);
    cudaGetSymbolAddress((void**)&pVlo, g_Vlo);

    cudaFuncSetAttribute(gemm_tc,  cudaFuncAttributeMaxDynamicSharedMemorySize, GEMM_SMEM_BYTES);
    cudaFuncSetAttribute(gemm_kv,  cudaFuncAttributeMaxDynamicSharedMemorySize, GEMM_SMEM_BYTES);
    cudaFuncSetAttribute(attn_mma, cudaFuncAttributeMaxDynamicSharedMemorySize, ATTN_SMEM_BYTES);

    const int M = BB * TT;  // 4096
    const int NBIG = M * CC / 4;
    const int NWQ  = CC * CC / 4;
    const int NWK  = NG * HD * CC / 4;

    conv_tf32<<<(NBIG + 255) / 256, 256>>>(q, pqc, NBIG);
    conv_tf32<<<(NBIG + 255) / 256, 256>>>(k, pkc, NBIG);
    conv_tf32<<<(NBIG + 255) / 256, 256>>>(v, pvc, NBIG);
    conv_tf32<<<(NWQ + 255) / 256, 256>>>(Wq, pwq, NWQ);
    conv_tf32<<<(NWK + 255) / 256, 256>>>(Wk, pwk, NWK);
    conv_tf32<<<(NWK + 255) / 256, 256>>>(Wv, pwv, NWK);
    conv_tf32<<<(NWQ + 255) / 256, 256>>>(Wp, pwp, NWQ);

    gemm_tc<<<dim3(CC / 128, M / 128), 256, GEMM_SMEM_BYTES>>>(pqc, pwq, nullptr, pQP, CC, CC);
    gemm_kv<<<dim3(8, M / 128), 256, GEMM_SMEM_BYTES>>>(pkc, pvc, pwk, pwv, pKhi, pKlo, pVP);
    pack_v<<<dim3(TT / 64, BB * NG), 256>>>(pVP, pVhi, pVlo);

    attn_mma<<<dim3(TT / 128, BB * NH), 256, ATTN_SMEM_BYTES>>>(pQP, pKhi, pKlo, pVhi, pVlo, pO);

    gemm_tc<<<dim3(CC / 128, M / 128), 256, GEMM_SMEM_BYTES>>>(pO, pwp, bp, out, CC, CC);
}

// round 8
// speedup vs baseline: 3.7962x; 1.0463x over previous
#include <cuda_runtime.h>
#include <cuda_bf16.h>
#include <cstdint>
#include <math.h>

#define BB 2
#define TT 2048
#define CC 2048
#define NH 32
#define NG 8
#define HD 64

// ---------------- scratch (no allocations allowed) ----------------
__device__ float g_QP[BB * TT * CC];
__device__ float g_VP[BB * TT * NG * HD];
__device__ float g_O [BB * TT * CC];
__device__ float g_qc[BB * TT * CC];
__device__ float g_kc[BB * TT * CC];
__device__ float g_vc[BB * TT * CC];
__device__ float g_wq[CC * CC];
__device__ float g_wk[NG * HD * CC];
__device__ float g_wv[NG * HD * CC];
__device__ float g_wp[CC * CC];
__device__ uint32_t g_Khi[BB * NG * TT * 32];
__device__ uint32_t g_Klo[BB * NG * TT * 32];
__device__ uint32_t g_Vhi[BB * NG * 64 * (TT / 2)];
__device__ uint32_t g_Vlo[BB * NG * 64 * (TT / 2)];

// ---------------- helpers ----------------
__device__ __forceinline__ uint32_t f2tf32(float x) {
    uint32_t r;
    asm("cvt.rna.tf32.f32 %0, %1;" : "=r"(r) : "f"(x));
    return r;
}
__device__ __forceinline__ float fast_ex2(float x) {
    float r;
    asm("ex2.approx.f32 %0, %1;" : "=f"(r) : "f"(x));
    return r;
}
__device__ __forceinline__ void mma_tf32(float& d0, float& d1, float& d2, float& d3,
                                         uint32_t a0, uint32_t a1, uint32_t a2, uint32_t a3,
                                         uint32_t b0, uint32_t b1)
{
    asm volatile(
        "mma.sync.aligned.m16n8k8.row.col.f32.tf32.tf32.f32 "
        "{%0,%1,%2,%3}, {%4,%5,%6,%7}, {%8,%9}, {%0,%1,%2,%3};"
        : "+f"(d0), "+f"(d1), "+f"(d2), "+f"(d3)
        : "r"(a0), "r"(a1), "r"(a2), "r"(a3), "r"(b0), "r"(b1));
}
__device__ __forceinline__ void mma_bf16(float* d,
                                         uint32_t a0, uint32_t a1, uint32_t a2, uint32_t a3,
                                         uint32_t b0, uint32_t b1)
{
    asm volatile(
        "mma.sync.aligned.m16n8k16.row.col.f32.bf16.bf16.f32 "
        "{%0,%1,%2,%3}, {%4,%5,%6,%7}, {%8,%9}, {%0,%1,%2,%3};"
        : "+f"(d[0]), "+f"(d[1]), "+f"(d[2]), "+f"(d[3])
        : "r"(a0), "r"(a1), "r"(a2), "r"(a3), "r"(b0), "r"(b1));
}
__device__ __forceinline__ uint32_t packbf2(float a, float b) {
    __nv_bfloat162 t = __floats2bfloat162_rn(a, b);
    return *(uint32_t*)&t;
}
__device__ __forceinline__ void split2(float a, float b, uint32_t& hi, uint32_t& lo) {
    __nv_bfloat16 ah = __float2bfloat16_rn(a);
    __nv_bfloat16 bh = __float2bfloat16_rn(b);
    float ar = a - __bfloat162float(ah);
    float br = b - __bfloat162float(bh);
    __nv_bfloat162 h; h.x = ah; h.y = bh;
    hi = *(uint32_t*)&h;
    lo = packbf2(ar, br);
}
__device__ __forceinline__ uint32_t smem_u32(const void* p) {
    uint32_t a;
    asm("{ .reg .u64 t; cvta.to.shared.u64 t, %1; cvt.u32.u64 %0, t; }" : "=r"(a) : "l"(p));
    return a;
}
__device__ __forceinline__ void cp16(uint32_t dst, const void* src) {
    asm volatile("cp.async.ca.shared.global [%0], [%1], 16;" :: "r"(dst), "l"(src));
}
__device__ __forceinline__ void cp_commit() { asm volatile("cp.async.commit_group;" ::: "memory"); }
template<int N> __device__ __forceinline__ void cp_wait() {
    asm volatile("cp.async.wait_group %0;" :: "n"(N) : "memory");
}

// ---------------- fused tf32 conversion: 7 tensors, one launch ----------------
#define NBIG4 (BB * TT * CC / 4)     // 2097152
#define NWQ4  (CC * CC / 4)          // 1048576
#define NWK4  (NG * HD * CC / 4)     // 262144

__global__ void __launch_bounds__(256) conv_all(
    const float* __restrict__ q, const float* __restrict__ k, const float* __restrict__ v,
    const float* __restrict__ Wq, const float* __restrict__ Wk,
    const float* __restrict__ Wv, const float* __restrict__ Wp,
    float* __restrict__ qc, float* __restrict__ kc, float* __restrict__ vc,
    float* __restrict__ wq, float* __restrict__ wk, float* __restrict__ wv,
    float* __restrict__ wp)
{
    const float* s; float* d; int n4;
    switch (blockIdx.y) {
        case 0: s = q;  d = qc; n4 = NBIG4; break;
        case 1: s = k;  d = kc; n4 = NBIG4; break;
        case 2: s = v;  d = vc; n4 = NBIG4; break;
        case 3: s = Wq; d = wq; n4 = NWQ4;  break;
        case 4: s = Wp; d = wp; n4 = NWQ4;  break;
        case 5: s = Wk; d = wk; n4 = NWK4;  break;
        default: s = Wv; d = wv; n4 = NWK4; break;
    }
    int i = blockIdx.x * 256 + threadIdx.x;
    if (i >= n4) return;
    float4 t = ((const float4*)s)[i];
    t.x = __uint_as_float(f2tf32(t.x));
    t.y = __uint_as_float(f2tf32(t.y));
    t.z = __uint_as_float(f2tf32(t.z));
    t.w = __uint_as_float(f2tf32(t.w));
    ((float4*)d)[i] = t;
}

// ---------------- V pack+transpose ----------------
__global__ void __launch_bounds__(256) pack_v(const float* __restrict__ VP,
                                              uint32_t* __restrict__ Vhi,
                                              uint32_t* __restrict__ Vlo)
{
    __shared__ float tile[64][65];
    const int bg = blockIdx.y;
    const int b  = bg >> 3, g = bg & 7;
    const int t0 = blockIdx.x * 64;
    const int tid = threadIdx.x;

#pragma unroll
    for (int it = 0; it < 4; it++) {
        int idx = tid + it * 256;
        int tl = idx >> 4, c4 = idx & 15;
        float4 v = *(const float4*)(VP + ((size_t)b * TT + t0 + tl) * (NG * HD) + g * 64 + c4 * 4);
        tile[tl][c4 * 4 + 0] = v.x; tile[tl][c4 * 4 + 1] = v.y;
        tile[tl][c4 * 4 + 2] = v.z; tile[tl][c4 * 4 + 3] = v.w;
    }
    __syncthreads();
#pragma unroll
    for (int it = 0; it < 8; it++) {
        int idx = tid + it * 256;
        int hd = idx >> 5, t2 = idx & 31;
        uint32_t hi, lo;
        split2(tile[2 * t2][hd], tile[2 * t2 + 1][hd], hi, lo);
        size_t o = ((size_t)bg * 64 + hd) * (TT / 2) + (t0 >> 1) + t2;
        Vhi[o] = hi;
        Vlo[o] = lo;
    }
}

// ============== tf32 GEMM: 256x128 CTA, 64x64 warp tile, 3-stage cp.async ==============
#define GST 24
#define A_ROWS 256
#define STGF ((A_ROWS + 128) * GST)          // 9216 floats = 36864 B / stage
#define NSTG 3
#define GEMM_SMEM_BYTES (NSTG * STGF * 4)    // 110592

__device__ __forceinline__ void gemm_body(
    const float* __restrict__ A, const float* __restrict__ Bm,
    const float* __restrict__ bias, float* __restrict__ Cm,
    int N, int K, int bm, int bn,
    uint32_t* __restrict__ Khi, uint32_t* __restrict__ Klo)
{
    extern __shared__ float smem[];
    const uint32_t smb = smem_u32(smem);

    const int tid  = threadIdx.x;
    const int wid  = tid >> 5;
    const int lane = tid & 31;
    const int grp  = lane >> 2;
    const int tig  = lane & 3;
    const int warp_m = wid >> 1;   // 0..3
    const int warp_n = wid & 1;    // 0..1

    const int srow = tid >> 2;          // 0..63
    const int scg  = (tid & 3) * 4;
    const float* Ag = A  + (size_t)(bm + srow) * K + scg;
    const float* Bg = Bm + (size_t)(bn + srow) * K + scg;

    float acc[4][8][4];
#pragma unroll
    for (int i = 0; i < 4; i++)
#pragma unroll
        for (int j = 0; j < 8; j++)
#pragma unroll
            for (int r = 0; r < 4; r++) acc[i][j][r] = 0.f;

    const int NS = K / 16;

#define GISSUE(sl, it) do {                                                             \
        const int _k0 = (it) * 16;                                                      \
        const uint32_t _sb = smb + (uint32_t)(sl) * (STGF * 4);                         \
        _Pragma("unroll")                                                               \
        for (int _j = 0; _j < 4; _j++)                                                  \
            cp16(_sb + (uint32_t)((srow + 64 * _j) * GST + scg) * 4,                    \
                 Ag + (size_t)(64 * _j) * K + _k0);                                     \
        _Pragma("unroll")                                                               \
        for (int _j = 0; _j < 2; _j++)                                                  \
            cp16(_sb + (uint32_t)((A_ROWS + srow + 64 * _j) * GST + scg) * 4,           \
                 Bg + (size_t)(64 * _j) * K + _k0);                                     \
    } while (0)

    GISSUE(0, 0); cp_commit();
    GISSUE(1, 1); cp_commit();

    for (int it = 0; it < NS; it++) {
        cp_wait<1>();
        __syncthreads();
        const int nxt = it + 2;
        if (nxt < NS) { GISSUE(nxt % NSTG, nxt); }
        cp_commit();

        const float* Sb  = smem + (it % NSTG) * STGF;
        const float* Bsb = Sb + A_ROWS * GST;
#pragma unroll
        for (int kk = 0; kk < 16; kk += 8) {
            uint2 bfr[8];
#pragma unroll
            for (int na = 0; na < 8; na++)
                bfr[na] = *(const uint2*)(Bsb + (warp_n * 64 + na * 8 + grp) * GST + kk + 2 * tig);
#pragma unroll
            for (int ma = 0; ma < 4; ma++) {
                uint2 av0 = *(const uint2*)(Sb + (warp_m * 64 + ma * 16 + grp) * GST + kk + 2 * tig);
                uint2 av1 = *(const uint2*)(Sb + (warp_m * 64 + ma * 16 + 8 + grp) * GST + kk + 2 * tig);
#pragma unroll
                for (int na = 0; na < 8; na++) {
                    mma_tf32(acc[ma][na][0], acc[ma][na][1], acc[ma][na][2], acc[ma][na][3],
                             av0.x, av1.x, av0.y, av1.y, bfr[na].x, bfr[na].y);
                }
            }
        }
    }
#undef GISSUE

    if (Khi) {
        // packed-K epilogue: word = adjacent hd pair; row -> (b, t)
#pragma unroll
        for (int na = 0; na < 8; na++) {
            const int col = bn + warp_n * 64 + na * 8 + 2 * tig;   // 0..511
            const int g   = col >> 6;
            const int wrd = (col & 63) >> 1;
#pragma unroll
            for (int ma = 0; ma < 4; ma++) {
                const int row = bm + warp_m * 64 + ma * 16 + grp;
                const int b = row >> 11, t = row & (TT - 1);
                size_t o = ((size_t)(b * NG + g) * TT + t) * 32 + wrd;
                uint32_t hi, lo;
                split2(acc[ma][na][0], acc[ma][na][1], hi, lo);
                Khi[o] = hi; Klo[o] = lo;
                split2(acc[ma][na][2], acc[ma][na][3], hi, lo);
                Khi[o + 8 * 32] = hi; Klo[o + 8 * 32] = lo;
            }
        }
    } else {
#pragma unroll
        for (int na = 0; na < 8; na++) {
            const int col = bn + warp_n * 64 + na * 8 + 2 * tig;
            float b0 = 0.f, b1 = 0.f;
            if (bias) { b0 = bias[col]; b1 = bias[col + 1]; }
#pragma unroll
            for (int ma = 0; ma < 4; ma++) {
                const int row = bm + warp_m * 64 + ma * 16 + grp;
                float2 v0 = make_float2(acc[ma][na][0] + b0, acc[ma][na][1] + b1);
                float2 v1 = make_float2(acc[ma][na][2] + b0, acc[ma][na][3] + b1);
                *(float2*)(Cm + (size_t)row * N + col) = v0;
                *(float2*)(Cm + (size_t)(row + 8) * N + col) = v1;
            }
        }
    }
}

__global__ void __launch_bounds__(256, 1) gemm_tc(
    const float* __restrict__ A, const float* __restrict__ Bm,
    const float* __restrict__ bias, float* __restrict__ Cm, int N, int K)
{
    gemm_body(A, Bm, bias, Cm, N, K, blockIdx.y * A_ROWS, blockIdx.x * 128, nullptr, nullptr);
}

__global__ void __launch_bounds__(256, 1) gemm_kv(
    const float* __restrict__ kc, const float* __restrict__ vc,
    const float* __restrict__ wk, const float* __restrict__ wv,
    uint32_t* __restrict__ Khi, uint32_t* __restrict__ Klo,
    float* __restrict__ VP)
{
    const bool isV = blockIdx.x >= 4;
    if (isV)
        gemm_body(vc, wv, nullptr, VP, NG * HD, CC, blockIdx.y * A_ROWS, (blockIdx.x & 3) * 128,
                  nullptr, nullptr);
    else
        gemm_body(kc, wk, nullptr, nullptr, NG * HD, CC, blockIdx.y * A_ROWS, (blockIdx.x & 3) * 128,
                  Khi, Klo);
}

// ============== flash attention: pre-packed K/V, cp.async ring, base-2 softmax ==============
#define QKST 40
#define VST  36
#define STW  9728
#define ATTN_SMEM_BYTES (2 * STW * 4)
#define QSCALE 0.1803365407f   // 0.125 * log2(e)

__global__ void __launch_bounds__(256, 1) attn_mma(
    const float* __restrict__ QP,
    const uint32_t* __restrict__ Kghi, const uint32_t* __restrict__ Kglo,
    const uint32_t* __restrict__ Vghi, const uint32_t* __restrict__ Vglo,
    float* __restrict__ O)
{
    extern __shared__ uint32_t sm[];
    const uint32_t smb = smem_u32(sm);

    const int bh = blockIdx.y;
    const int b  = bh >> 5;
    const int h  = bh & 31;
    const int g  = h & 7;
    const int bg = b * NG + g;
    const int q0 = blockIdx.x * 128;

    const float* Qg = QP + ((size_t)b * TT + q0) * CC + h * HD;
    const uint32_t* Kh = Kghi + (size_t)bg * TT * 32;
    const uint32_t* Kl = Kglo + (size_t)bg * TT * 32;
    const uint32_t* Vh = Vghi + (size_t)bg * 64 * (TT / 2);
    const uint32_t* Vl = Vglo + (size_t)bg * 64 * (TT / 2);

    const int tid  = threadIdx.x;
    const int wid  = tid >> 5;
    const int lane = tid & 31;
    const int grp  = lane >> 2;
    const int tig  = lane & 3;
    const int m0   = wid * 16;

#define ATTN_ISSUE(s, kv) do {                                                            \
        _Pragma("unroll")                                                                 \
        for (int _it = 0; _it < 4; _it++) {                                               \
            int _ch = tid + _it * 256;                                                    \
            int _arr = _ch >> 9, _rem = _ch & 511;                                        \
            int _r = _rem >> 3, _c = _rem & 7;                                            \
            const uint32_t* _src = (_arr ? Kl : Kh) + ((size_t)((kv) + _r) * 32 + _c * 4);\
            cp16(smb + (uint32_t)((s) * STW + _arr * 2560 + _r * QKST + _c * 4) * 4, _src);\
        }                                                                                 \
        _Pragma("unroll")                                                                 \
        for (int _it = 0; _it < 4; _it++) {                                               \
            int _ch = tid + _it * 256;                                                    \
            int _arr = _ch >> 9, _rem = _ch & 511;                                        \
            int _hd = _rem >> 3, _c = _rem & 7;                                           \
            const uint32_t* _src = (_arr ? Vl : Vh) + ((size_t)_hd * (TT / 2) + ((kv) >> 1) + _c * 4);\
            cp16(smb + (uint32_t)((s) * STW + 5120 + _arr * 2304 + _hd * VST + _c * 4) * 4, _src);\
        }                                                                                 \
    } while (0)

    ATTN_ISSUE(0, 0);  cp_commit();
    ATTN_ISSUE(1, 64); cp_commit();

    // Q fragments straight from gmem, scaled into the base-2 domain
    uint32_t qa_h[4][4], qa_l[4][4];
#pragma unroll
    for (int c = 0; c < 4; c++) {
#pragma unroll
        for (int rr = 0; rr < 2; rr++) {
            const int row = m0 + grp + rr * 8;
            float4 v = *(const float4*)(Qg + (size_t)row * CC + 16 * c + 4 * tig);
            v.x *= QSCALE; v.y *= QSCALE; v.z *= QSCALE; v.w *= QSCALE;
            uint32_t h0, l0, h1, l1;
            split2(v.x, v.y, h0, l0);
            split2(v.z, v.w, h1, l1);
            qa_h[c][rr] = h0; qa_h[c][rr + 2] = h1;
            qa_l[c][rr] = l0; qa_l[c][rr + 2] = l1;
        }
    }

    float oacc[8][4];
#pragma unroll
    for (int i = 0; i < 8; i++)
#pragma unroll
        for (int j = 0; j < 4; j++) oacc[i][j] = 0.f;
    float m_r0 = -INFINITY, m_r1 = -INFINITY, l_r0 = 0.f, l_r1 = 0.f;

    for (int tile = 0; tile < TT / 64; tile++) {
        cp_wait<1>();
        __syncthreads();
        const int s = tile & 1;
        const uint32_t* Khi = sm + s * STW;
        const uint32_t* Klo = Khi + 2560;
        const uint32_t* Vhi = Khi + 5120;
        const uint32_t* Vlo = Khi + 7424;

        float sacc[8][4];
#pragma unroll
        for (int i = 0; i < 8; i++)
#pragma unroll
            for (int j = 0; j < 4; j++) sacc[i][j] = 0.f;
#pragma unroll
        for (int c = 0; c < 4; c++) {
#pragma unroll
            for (int gg = 0; gg < 8; gg++) {
                const int rowk = (8 * gg + grp) * QKST + 8 * c + 2 * tig;
                uint2 kh = *(const uint2*)(Khi + rowk);
                uint2 kl = *(const uint2*)(Klo + rowk);
                mma_bf16(sacc[gg], qa_h[c][0], qa_h[c][1], qa_h[c][2], qa_h[c][3], kh.x, kh.y);
                mma_bf16(sacc[gg], qa_h[c][0], qa_h[c][1], qa_h[c][2], qa_h[c][3], kl.x, kl.y);
                mma_bf16(sacc[gg], qa_l[c][0], qa_l[c][1], qa_l[c][2], qa_l[c][3], kh.x, kh.y);
            }
        }

        // online softmax (base 2)
        float rm0 = -INFINITY, rm1 = -INFINITY;
#pragma unroll
        for (int gg = 0; gg < 8; gg++) {
            rm0 = fmaxf(rm0, fmaxf(sacc[gg][0], sacc[gg][1]));
            rm1 = fmaxf(rm1, fmaxf(sacc[gg][2], sacc[gg][3]));
        }
        rm0 = fmaxf(rm0, __shfl_xor_sync(0xffffffffu, rm0, 1));
        rm0 = fmaxf(rm0, __shfl_xor_sync(0xffffffffu, rm0, 2));
        rm1 = fmaxf(rm1, __shfl_xor_sync(0xffffffffu, rm1, 1));
        rm1 = fmaxf(rm1, __shfl_xor_sync(0xffffffffu, rm1, 2));

        float nm0 = fmaxf(m_r0, rm0), nm1 = fmaxf(m_r1, rm1);
        float sc0 = fast_ex2(m_r0 - nm0), sc1 = fast_ex2(m_r1 - nm1);
        m_r0 = nm0; m_r1 = nm1;

        float rs0 = 0.f, rs1 = 0.f;
#pragma unroll
        for (int gg = 0; gg < 8; gg++) {
            sacc[gg][0] = fast_ex2(sacc[gg][0] - nm0);
            sacc[gg][1] = fast_ex2(sacc[gg][1] - nm0);
            sacc[gg][2] = fast_ex2(sacc[gg][2] - nm1);
            sacc[gg][3] = fast_ex2(sacc[gg][3] - nm1);
            rs0 += sacc[gg][0] + sacc[gg][1];
            rs1 += sacc[gg][2] + sacc[gg][3];
        }
        rs0 += __shfl_xor_sync(0xffffffffu, rs0, 1);
        rs0 += __shfl_xor_sync(0xffffffffu, rs0, 2);
        rs1 += __shfl_xor_sync(0xffffffffu, rs1, 1);
        rs1 += __shfl_xor_sync(0xffffffffu, rs1, 2);
        l_r0 = l_r0 * sc0 + rs0;
        l_r1 = l_r1 * sc1 + rs1;
#pragma unroll
        for (int i = 0; i < 8; i++) {
            oacc[i][0] *= sc0; oacc[i][1] *= sc0;
            oacc[i][2] *= sc1; oacc[i][3] *= sc1;
        }

        uint32_t phi[8][2], plo[8][2];
#pragma unroll
        for (int gg = 0; gg < 8; gg++) {
            split2(sacc[gg][0], sacc[gg][1], phi[gg][0], plo[gg][0]);
            split2(sacc[gg][2], sacc[gg][3], phi[gg][1], plo[gg][1]);
        }

#pragma unroll
        for (int c = 0; c < 4; c++) {
            uint32_t ah0 = phi[2 * c][0],     ah1 = phi[2 * c][1];
            uint32_t ah2 = phi[2 * c + 1][0], ah3 = phi[2 * c + 1][1];
            uint32_t al0 = plo[2 * c][0],     al1 = plo[2 * c][1];
            uint32_t al2 = plo[2 * c + 1][0], al3 = plo[2 * c + 1][1];
#pragma unroll
            for (int hh = 0; hh < 8; hh++) {
                const int rowv = (8 * hh + grp) * VST + 8 * c + tig;
                uint32_t bh0 = Vhi[rowv], bh1 = Vhi[rowv + 4];
                uint32_t bl0 = Vlo[rowv], bl1 = Vlo[rowv + 4];
                mma_bf16(oacc[hh], ah0, ah1, ah2, ah3, bh0, bh1);
                mma_bf16(oacc[hh], ah0, ah1, ah2, ah3, bl0, bl1);
                mma_bf16(oacc[hh], al0, al1, al2, al3, bh0, bh1);
            }
        }

        __syncthreads();
        if (tile + 2 < TT / 64) { ATTN_ISSUE(s, (tile + 2) * 64); }
        cp_commit();
    }
#undef ATTN_ISSUE

    const float inv0 = 1.0f / l_r0, inv1 = 1.0f / l_r1;
    float* Og = O + ((size_t)b * TT + q0) * CC + h * HD;
    const int r0 = m0 + grp, r1 = m0 + grp + 8;
#pragma unroll
    for (int hh = 0; hh < 8; hh++) {
        const int col = 8 * hh + 2 * tig;
        float2 v0 = make_float2(__uint_as_float(f2tf32(oacc[hh][0] * inv0)),
                                __uint_as_float(f2tf32(oacc[hh][1] * inv0)));
        float2 v1 = make_float2(__uint_as_float(f2tf32(oacc[hh][2] * inv1)),
                                __uint_as_float(f2tf32(oacc[hh][3] * inv1)));
        *(float2*)(Og + (size_t)r0 * CC + col) = v0;
        *(float2*)(Og + (size_t)r1 * CC + col) = v1;
    }
}

// ---------------- launch ----------------
extern "C" void kernel_launch(void* const* d_in, const int* in_sizes, int n_in,
                              void* d_out, int out_size)
{
    const float* q  = (const float*)d_in[0];
    const float* k  = (const float*)d_in[1];
    const float* v  = (const float*)d_in[2];
    const float* Wq = (const float*)d_in[3];
    const float* Wk = (const float*)d_in[4];
    const float* Wv = (const float*)d_in[5];
    const float* Wp = (const float*)d_in[6];
    const float* bp = (const float*)d_in[7];
    float* out = (float*)d_out;

    float *pQP, *pVP, *pO, *pqc, *pkc, *pvc, *pwq, *pwk, *pwv, *pwp;
    uint32_t *pKhi, *pKlo, *pVhi, *pVlo;
    cudaGetSymbolAddress((void**)&pQP, g_QP);
    cudaGetSymbolAddress((void**)&pVP, g_VP);
    cudaGetSymbolAddress((void**)&pO,  g_O);
    cudaGetSymbolAddress((void**)&pqc, g_qc);
    cudaGetSymbolAddress((void**)&pkc, g_kc);
    cudaGetSymbolAddress((void**)&pvc, g_vc);
    cudaGetSymbolAddress((void**)&pwq, g_wq);
    cudaGetSymbolAddress((void**)&pwk, g_wk);
    cudaGetSymbolAddress((void**)&pwv, g_wv);
    cudaGetSymbolAddress((void**)&pwp, g_wp);
    cudaGetSymbolAddress((void**)&pKhi, g_Khi);
    cudaGetSymbolAddress((void**)&pKlo, g_Klo);
    cudaGetSymbolAddress((void**)&pVhi, g_Vhi);
    cudaGetSymbolAddress((void**)&pVlo, g_Vlo);

    cudaFuncSetAttribute(gemm_tc,  cudaFuncAttributeMaxDynamicSharedMemorySize, GEMM_SMEM_BYTES);
    cudaFuncSetAttribute(gemm_kv,  cudaFuncAttributeMaxDynamicSharedMemorySize, GEMM_SMEM_BYTES);
    cudaFuncSetAttribute(attn_mma, cudaFuncAttributeMaxDynamicSharedMemorySize, ATTN_SMEM_BYTES);

    const int M = BB * TT;  // 4096

    // fused tf32 pre-conversion (all 7 tensors, one launch)
    conv_all<<<dim3(NBIG4 / 256, 7), 256>>>(q, k, v, Wq, Wk, Wv, Wp,
                                            pqc, pkc, pvc, pwq, pwk, pwv, pwp);

    gemm_tc<<<dim3(CC / 128, M / A_ROWS), 256, GEMM_SMEM_BYTES>>>(pqc, pwq, nullptr, pQP, CC, CC);
    gemm_kv<<<dim3(8, M / A_ROWS), 256, GEMM_SMEM_BYTES>>>(pkc, pvc, pwk, pwv, pKhi, pKlo, pVP);
    pack_v<<<dim3(TT / 64, BB * NG), 256>>>(pVP, pVhi, pVlo);

    attn_mma<<<dim3(TT / 128, BB * NH), 256, ATTN_SMEM_BYTES>>>(pQP, pKhi, pKlo, pVhi, pVlo, pO);

    gemm_tc<<<dim3(CC / 128, M / A_ROWS), 256, GEMM_SMEM_BYTES>>>(pO, pwp, bp, out, CC, CC);
}